// round 6
// baseline (speedup 1.0000x reference)
#include <cuda_runtime.h>
#include <cuda_fp16.h>
#include <cstdint>

#define N_ROWS 32768
#define D 64
#define K 1024
#define KPAD 88            // padded k-extent in halfs; row stride 176 B (conflict-free ldmatrix)
#define ROWB 176
#define TM 128             // rows per CTA
#define MARGIN_COARSE 4e-3f

__device__ float d_en[K];                        // fp32 ||e_k||^2 (ref-style mul-then-add)
__device__ float d_eT[K * D];                    // [k][d] fp32 (exact / gather)
__device__ __align__(16) __half d_Bh[K * KPAD];  // [k][KPAD] fp16 codebook (+aug en at col 64)
__device__ int   d_idx[N_ROWS];
__device__ float d_lossAcc;
__device__ int   d_flagCnt;
__device__ int   d_flagList[N_ROWS];

// ---------------- helpers ----------------
__device__ __forceinline__ uint32_t smem_u32(const void* p) {
    uint32_t a;
    asm("{ .reg .u64 t; cvta.to.shared.u64 t, %1; cvt.u32.u64 %0, t; }" : "=r"(a) : "l"(p));
    return a;
}
__device__ __forceinline__ void ldm_x4(uint32_t* r, uint32_t addr) {
    asm volatile("ldmatrix.sync.aligned.m8n8.x4.shared.b16 {%0,%1,%2,%3}, [%4];"
        : "=r"(r[0]), "=r"(r[1]), "=r"(r[2]), "=r"(r[3]) : "r"(addr));
}
__device__ __forceinline__ void mma_f16(float* d, const uint32_t* a, const uint32_t* b) {
    asm volatile("mma.sync.aligned.m16n8k16.row.col.f32.f16.f16.f32 "
        "{%0,%1,%2,%3}, {%4,%5,%6,%7}, {%8,%9}, {%0,%1,%2,%3};"
        : "+f"(d[0]), "+f"(d[1]), "+f"(d[2]), "+f"(d[3])
        : "r"(a[0]), "r"(a[1]), "r"(a[2]), "r"(a[3]), "r"(b[0]), "r"(b[1]));
}
__device__ __forceinline__ void cp_async16(uint32_t sdst, const void* gsrc) {
    asm volatile("cp.async.cg.shared.global [%0], [%1], 16;" :: "r"(sdst), "l"(gsrc) : "memory");
}
__device__ __forceinline__ void cp_commit() { asm volatile("cp.async.commit_group;" ::: "memory"); }
__device__ __forceinline__ void cp_wait0()  { asm volatile("cp.async.wait_group 0;" ::: "memory"); }

// float-float (double-single) primitives — full-rate FMA pipe, ~1e-14 accuracy
__device__ __forceinline__ void twoSum(float a, float b, float& s, float& e) {
    s = __fadd_rn(a, b);
    float bb = __fsub_rn(s, a);
    e = __fadd_rn(__fsub_rn(a, __fsub_rn(s, bb)), __fsub_rn(b, bb));
}
__device__ __forceinline__ void ddAccum(float& s, float& c, float x, float e) {
    float p = __fmul_rn(x, e);
    float perr = __fmaf_rn(x, e, -p);
    float t, err;
    twoSum(s, p, t, err);
    s = t;
    c = __fadd_rn(c, __fadd_rn(err, perr));
}

// ---------------- Kernel A (idx 0): norms + transpose ----------------
__global__ void prep1_kernel(const float* __restrict__ emb) {
    int k = blockIdx.x * blockDim.x + threadIdx.x;
    if (k < K) {
        float s = 0.0f;
        float fbuf[4];
        for (int dd = 0; dd < D; dd += 4) {
            #pragma unroll
            for (int u = 0; u < 4; u++) {
                float v = emb[(dd + u) * K + k];            // coalesced across lanes
                s = __fadd_rn(s, __fmul_rn(v, v));          // ref-style mul-then-add
                fbuf[u] = v;
            }
            *(float4*)(d_eT + k * D + dd) = make_float4(fbuf[0], fbuf[1], fbuf[2], fbuf[3]);
        }
        d_en[k] = s;
    }
}

// ---------------- Kernel B (idx 1): fp16 pack + aug column ----------------
__global__ void prep2_kernel() {
    int k = blockIdx.x * blockDim.x + threadIdx.x;
    if (k < K) {
        float s = d_en[k];
        for (int dd = 0; dd < D; dd += 4) {
            float4 v = *(const float4*)(d_eT + k * D + dd);
            __half h0 = __float2half(v.x), h1 = __float2half(v.y);
            __half h2 = __float2half(v.z), h3 = __float2half(v.w);
            *(uint2*)(d_Bh + k * KPAD + dd) = make_uint2(
                (uint32_t)__half_as_ushort(h0) | ((uint32_t)__half_as_ushort(h1) << 16),
                (uint32_t)__half_as_ushort(h2) | ((uint32_t)__half_as_ushort(h3) << 16));
        }
        *(uint2*)(d_Bh + k * KPAD + 64) = make_uint2((uint32_t)__half_as_ushort(__float2half(s)), 0u);
        *(uint2*)(d_Bh + k * KPAD + 68) = make_uint2(0u, 0u);
        *(uint4*)(d_Bh + k * KPAD + 72) = make_uint4(0u, 0u, 0u, 0u);
        *(uint4*)(d_Bh + k * KPAD + 80) = make_uint4(0u, 0u, 0u, 0u);
    }
}

// ---------------- Kernel C (idx 2): zero accumulators ----------------
__global__ void prep3_kernel() {
    d_lossAcc = 0.0f;
    d_flagCnt = 0;
}

// ---------------- Kernel D (idx 3): fp16 HMMA coarse + fused argmin ----------------
#define S_A   0
#define S_B   22528
#define PLANE 11264
#define S_TOTAL 45056

__global__ __launch_bounds__(256, 2)
void gemm_argmin_kernel(const float* __restrict__ x) {
    extern __shared__ char smem[];
    uint32_t sb = smem_u32(smem);
    int tid = threadIdx.x;
    int lane = tid & 31, warp = tid >> 5;
    int m0 = warp * 16;
    int row0 = blockIdx.x * TM;

    // A: x rows -> fp16 of (-2x), padded, aug col 64 = 1.0
    #pragma unroll
    for (int i = 0; i < 8; i++) {
        int f = tid + i * 256;          // 2048 float4 = 128 rows x 16
        int row = f >> 4, j = f & 15;
        float4 v = *(const float4*)(x + (row0 + row) * D + 4 * j);
        __half h0 = __float2half(-2.0f * v.x), h1 = __float2half(-2.0f * v.y);
        __half h2 = __float2half(-2.0f * v.z), h3 = __float2half(-2.0f * v.w);
        *(uint2*)(smem + S_A + (uint32_t)row * ROWB + j * 8) = make_uint2(
            (uint32_t)__half_as_ushort(h0) | ((uint32_t)__half_as_ushort(h1) << 16),
            (uint32_t)__half_as_ushort(h2) | ((uint32_t)__half_as_ushort(h3) << 16));
    }
    if (tid < 128) {
        uint32_t base = S_A + (uint32_t)tid * ROWB + 128;   // byte offset of col 64
        *(uint4*)(smem + base)      = make_uint4(0x3C00u, 0u, 0u, 0u);   // 1.0h, zeros
        *(uint4*)(smem + base + 16) = make_uint4(0u, 0u, 0u, 0u);
        *(uint4*)(smem + base + 32) = make_uint4(0u, 0u, 0u, 0u);
    }

    auto loadB = [&](int chunk) {
        uint32_t dst = sb + S_B + (uint32_t)(chunk & 1) * PLANE;
        const char* src = (const char*)(d_Bh + chunk * 64 * KPAD);
        #pragma unroll
        for (int i = 0; i < 3; i++) {
            int u = tid + i * 256;                 // 704 16B units
            if (u < 704) cp_async16(dst + 16 * u, src + 16 * u);
        }
        cp_commit();
    };

    loadB(0);
    cp_wait0();
    __syncthreads();

    int r = lane & 7, q = lane >> 3;
    uint32_t aAddr = sb + S_A + (uint32_t)(m0 + r + ((q & 1) << 3)) * ROWB + ((q >> 1) << 4);
    uint32_t bOff = (uint32_t)(r + ((q >> 1) << 3)) * ROWB + ((q & 1) << 4);

    uint32_t ah[5][4];
    #pragma unroll
    for (int k = 0; k < 5; k++) ldm_x4(ah[k], aAddr + k * 32);

    float bA = 3.4e38f, b2A = 3.4e38f, bB = 3.4e38f, b2B = 3.4e38f;
    int iA = 0, iB = 0;

    #pragma unroll 1
    for (int c = 0; c < 16; c++) {
        if (c < 15) loadB(c + 1);     // async prefetch into other buffer

        uint32_t bbase = sb + S_B + (uint32_t)(c & 1) * PLANE + bOff;

        float acc[8][4];
        #pragma unroll
        for (int nb = 0; nb < 8; nb++)
            #pragma unroll
            for (int j = 0; j < 4; j++) acc[nb][j] = 0.0f;

        #pragma unroll
        for (int k = 0; k < 5; k++) {
            #pragma unroll
            for (int t = 0; t < 4; t++) {
                uint32_t bh[4];
                ldm_x4(bh, bbase + t * (16 * ROWB) + k * 32);
                mma_f16(acc[2*t],   ah[k], bh);
                mma_f16(acc[2*t+1], ah[k], bh + 2);
            }
        }

        int kbase = c * 64 + 2 * (lane & 3);
        #pragma unroll
        for (int nb = 0; nb < 8; nb++) {
            #pragma unroll
            for (int j = 0; j < 4; j++) {
                float v = acc[nb][j];
                int kidx = kbase + nb * 8 + (j & 1);
                if (j < 2) {
                    if (v < bA) { b2A = bA; bA = v; iA = kidx; } else b2A = fminf(b2A, v);
                } else {
                    if (v < bB) { b2B = bB; bB = v; iB = kidx; } else b2B = fminf(b2B, v);
                }
            }
        }
        cp_wait0();
        __syncthreads();
    }

    #pragma unroll
    for (int off = 1; off <= 2; off <<= 1) {
        float ov = __shfl_xor_sync(0xffffffff, bA, off);
        float ov2 = __shfl_xor_sync(0xffffffff, b2A, off);
        int   oi = __shfl_xor_sync(0xffffffff, iA, off);
        if (ov < bA) { b2A = fminf(bA, ov2); bA = ov; iA = oi; } else b2A = fminf(b2A, ov);
        ov = __shfl_xor_sync(0xffffffff, bB, off);
        ov2 = __shfl_xor_sync(0xffffffff, b2B, off);
        oi = __shfl_xor_sync(0xffffffff, iB, off);
        if (ov < bB) { b2B = fminf(bB, ov2); bB = ov; iB = oi; } else b2B = fminf(b2B, ov);
    }
    if ((lane & 3) == 0) {
        int rowA = row0 + m0 + (lane >> 2);
        d_idx[rowA] = iA;
        if (b2A - bA < MARGIN_COARSE) { int p = atomicAdd(&d_flagCnt, 1); d_flagList[p] = rowA; }
        int rowB = rowA + 8;
        d_idx[rowB] = iB;
        if (b2B - bB < MARGIN_COARSE) { int p = atomicAdd(&d_flagCnt, 1); d_flagList[p] = rowB; }
    }
}

// ---------------- Kernel E (idx 4): exact float-float resolve, ref-grid rounding ----------------
// Block per flagged row. sim in double-single on FMA pipe; then the reference's
// fp32 op sequence: dist = fl32( fl32(xn + en_k) - fl32(2*sim) ), first-index min.
__global__ __launch_bounds__(256, 1)
void exact_kernel(const float* __restrict__ x) {
    __shared__ float sx[D];
    __shared__ float sxn;
    __shared__ float rv[256];
    __shared__ int   ri[256];
    int tid = threadIdx.x;

    int cnt = d_flagCnt;
    for (int i = blockIdx.x; i < cnt; i += gridDim.x) {
        int row = d_flagList[i];
        if (tid < D / 4) {
            float4 v = *(const float4*)(x + row * D + 4 * tid);
            sx[4*tid] = v.x; sx[4*tid+1] = v.y; sx[4*tid+2] = v.z; sx[4*tid+3] = v.w;
        }
        __syncthreads();
        if (tid == 0) {
            float a = 0.0f;
            for (int dd = 0; dd < D; dd++)
                a = __fadd_rn(a, __fmul_rn(sx[dd], sx[dd]));   // ref-style norm
            sxn = a;
        }
        __syncthreads();
        float xn = sxn;

        int k0 = tid * 4;
        float s0 = 0.f, c0 = 0.f, s1 = 0.f, c1 = 0.f;
        float s2 = 0.f, c2 = 0.f, s3 = 0.f, c3 = 0.f;
        const float* e0 = d_eT + (k0 + 0) * D;
        const float* e1 = d_eT + (k0 + 1) * D;
        const float* e2 = d_eT + (k0 + 2) * D;
        const float* e3 = d_eT + (k0 + 3) * D;
        #pragma unroll 4
        for (int dd = 0; dd < D; dd++) {
            float xv = sx[dd];
            ddAccum(s0, c0, xv, e0[dd]);
            ddAccum(s1, c1, xv, e1[dd]);
            ddAccum(s2, c2, xv, e2[dd]);
            ddAccum(s3, c3, xv, e3[dd]);
        }
        float ss[4] = {s0, s1, s2, s3};
        float cc[4] = {c0, c1, c2, c3};
        float bv = 3.4e38f; int bi = 0;
        #pragma unroll
        for (int t = 0; t < 4; t++) {
            // fl32(2*sim): renormalize then fold the compensation in
            float hi, lo;
            twoSum(ss[t], cc[t], hi, lo);
            float s2f = __fmaf_rn(2.0f, lo, __fmul_rn(2.0f, hi));
            float t1 = __fadd_rn(xn, d_en[k0 + t]);
            float dist = __fsub_rn(t1, s2f);
            if (dist < bv) { bv = dist; bi = k0 + t; }
        }
        rv[tid] = bv; ri[tid] = bi;
        __syncthreads();
        for (int off = 128; off > 0; off >>= 1) {
            if (tid < off) {
                float ov = rv[tid + off]; int oi = ri[tid + off];
                if (ov < rv[tid] || (ov == rv[tid] && oi < ri[tid])) {
                    rv[tid] = ov; ri[tid] = oi;
                }
            }
            __syncthreads();
        }
        if (tid == 0) d_idx[row] = ri[0];
        __syncthreads();
    }
}

// ---------------- Kernel F (idx 5): gather + straight-through + loss ----------------
__global__ void out_kernel(const float* __restrict__ x, float* __restrict__ out) {
    int t = blockIdx.x * blockDim.x + threadIdx.x;   // float4 index
    int r = t >> 4, j = t & 15;
    int idx = d_idx[r];
    float4 xv = ((const float4*)x)[t];
    float4 qv = *(const float4*)(d_eT + idx * D + 4 * j);
    float dx = qv.x - xv.x, dy = qv.y - xv.y, dz = qv.z - xv.z, dw = qv.w - xv.w;
    ((float4*)out)[t] = make_float4(xv.x + dx, xv.y + dy, xv.z + dz, xv.w + dw);
    float v = dx * dx + dy * dy + dz * dz + dw * dw;

    #pragma unroll
    for (int off = 16; off > 0; off >>= 1) v += __shfl_xor_sync(0xffffffff, v, off);
    __shared__ float ws[8];
    int wid = threadIdx.x >> 5, lid = threadIdx.x & 31;
    if (lid == 0) ws[wid] = v;
    __syncthreads();
    if (threadIdx.x == 0) {
        float s = 0.0f;
        #pragma unroll
        for (int i = 0; i < 8; i++) s += ws[i];
        atomicAdd(&d_lossAcc, s);
    }
}

// ---------------- Kernel G (idx 6): finalize loss ----------------
__global__ void fin_kernel(float* __restrict__ out, int out_size) {
    out[out_size - 1] = 1.25f * d_lossAcc * (1.0f / (float)(N_ROWS * D));
}

extern "C" void kernel_launch(void* const* d_in, const int* in_sizes, int n_in,
                              void* d_out, int out_size) {
    const float* x   = (const float*)d_in[0];
    const float* emb = (const float*)d_in[1];
    float* out = (float*)d_out;

    prep1_kernel<<<4, 256>>>(emb);                       // idx 0
    prep2_kernel<<<4, 256>>>();                          // idx 1
    prep3_kernel<<<1, 1>>>();                            // idx 2
    gemm_argmin_kernel<<<N_ROWS / TM, 256, S_TOTAL>>>(x);// idx 3  (profiled)
    exact_kernel<<<256, 256>>>(x);                       // idx 4
    out_kernel<<<(N_ROWS * D / 4) / 256, 256>>>(x, out); // idx 5
    fin_kernel<<<1, 1>>>(out, out_size);                 // idx 6
}

// round 7
// speedup vs baseline: 3.9792x; 3.9792x over previous
#include <cuda_runtime.h>
#include <cuda_fp16.h>
#include <cstdint>

#define N_ROWS 32768
#define D 64
#define K 1024
#define KPAD 88            // padded k-extent in halfs; row stride 176 B (conflict-free ldmatrix)
#define ROWB 176
#define TM 128             // rows per CTA
#define MARGIN_COARSE 4e-3f

__device__ float d_en[K];                        // fp32 ||e_k||^2 (ref-style mul-then-add)
__device__ float d_eT[K * D];                    // [k][d] fp32 (gather)
__device__ __align__(16) __half d_Bh[K * KPAD];  // [k][KPAD] fp16 codebook (+aug en at col 64)
__device__ int   d_idx[N_ROWS];
__device__ float d_lossAcc;
__device__ int   d_flagCnt;
__device__ int   d_flagList[N_ROWS];

// ---------------- helpers ----------------
__device__ __forceinline__ uint32_t smem_u32(const void* p) {
    uint32_t a;
    asm("{ .reg .u64 t; cvta.to.shared.u64 t, %1; cvt.u32.u64 %0, t; }" : "=r"(a) : "l"(p));
    return a;
}
__device__ __forceinline__ void ldm_x4(uint32_t* r, uint32_t addr) {
    asm volatile("ldmatrix.sync.aligned.m8n8.x4.shared.b16 {%0,%1,%2,%3}, [%4];"
        : "=r"(r[0]), "=r"(r[1]), "=r"(r[2]), "=r"(r[3]) : "r"(addr));
}
__device__ __forceinline__ void mma_f16(float* d, const uint32_t* a, const uint32_t* b) {
    asm volatile("mma.sync.aligned.m16n8k16.row.col.f32.f16.f16.f32 "
        "{%0,%1,%2,%3}, {%4,%5,%6,%7}, {%8,%9}, {%0,%1,%2,%3};"
        : "+f"(d[0]), "+f"(d[1]), "+f"(d[2]), "+f"(d[3])
        : "r"(a[0]), "r"(a[1]), "r"(a[2]), "r"(a[3]), "r"(b[0]), "r"(b[1]));
}
__device__ __forceinline__ void cp_async16(uint32_t sdst, const void* gsrc) {
    asm volatile("cp.async.cg.shared.global [%0], [%1], 16;" :: "r"(sdst), "l"(gsrc) : "memory");
}
__device__ __forceinline__ void cp_commit() { asm volatile("cp.async.commit_group;" ::: "memory"); }
__device__ __forceinline__ void cp_wait0()  { asm volatile("cp.async.wait_group 0;" ::: "memory"); }

// float-float (double-single) primitives — full-rate FMA pipe, ~1e-14 accuracy
__device__ __forceinline__ void twoSum(float a, float b, float& s, float& e) {
    s = __fadd_rn(a, b);
    float bb = __fsub_rn(s, a);
    e = __fadd_rn(__fsub_rn(a, __fsub_rn(s, bb)), __fsub_rn(b, bb));
}
__device__ __forceinline__ void ddAccum(float& s, float& c, float x, float e) {
    float p = __fmul_rn(x, e);
    float perr = __fmaf_rn(x, e, -p);
    float t, err;
    twoSum(s, p, t, err);
    s = t;
    c = __fadd_rn(c, __fadd_rn(err, perr));
}

// ---------------- Kernel A (idx 0): norms + transpose ----------------
__global__ void prep1_kernel(const float* __restrict__ emb) {
    int k = blockIdx.x * blockDim.x + threadIdx.x;
    if (k < K) {
        float s = 0.0f;
        float fbuf[4];
        for (int dd = 0; dd < D; dd += 4) {
            #pragma unroll
            for (int u = 0; u < 4; u++) {
                float v = emb[(dd + u) * K + k];            // coalesced across lanes
                s = __fadd_rn(s, __fmul_rn(v, v));          // ref-style mul-then-add
                fbuf[u] = v;
            }
            *(float4*)(d_eT + k * D + dd) = make_float4(fbuf[0], fbuf[1], fbuf[2], fbuf[3]);
        }
        d_en[k] = s;
    }
}

// ---------------- Kernel B (idx 1): fp16 pack + aug column ----------------
__global__ void prep2_kernel() {
    int k = blockIdx.x * blockDim.x + threadIdx.x;
    if (k < K) {
        float s = d_en[k];
        for (int dd = 0; dd < D; dd += 4) {
            float4 v = *(const float4*)(d_eT + k * D + dd);
            __half h0 = __float2half(v.x), h1 = __float2half(v.y);
            __half h2 = __float2half(v.z), h3 = __float2half(v.w);
            *(uint2*)(d_Bh + k * KPAD + dd) = make_uint2(
                (uint32_t)__half_as_ushort(h0) | ((uint32_t)__half_as_ushort(h1) << 16),
                (uint32_t)__half_as_ushort(h2) | ((uint32_t)__half_as_ushort(h3) << 16));
        }
        *(uint2*)(d_Bh + k * KPAD + 64) = make_uint2((uint32_t)__half_as_ushort(__float2half(s)), 0u);
        *(uint2*)(d_Bh + k * KPAD + 68) = make_uint2(0u, 0u);
        *(uint4*)(d_Bh + k * KPAD + 72) = make_uint4(0u, 0u, 0u, 0u);
        *(uint4*)(d_Bh + k * KPAD + 80) = make_uint4(0u, 0u, 0u, 0u);
    }
}

// ---------------- Kernel C (idx 2): zero accumulators ----------------
__global__ void prep3_kernel() {
    d_lossAcc = 0.0f;
    d_flagCnt = 0;
}

// ---------------- Kernel D (idx 3): fp16 HMMA coarse + fused argmin ----------------
#define S_A   0
#define S_B   22528
#define PLANE 11264
#define S_TOTAL 45056

__global__ __launch_bounds__(256, 2)
void gemm_argmin_kernel(const float* __restrict__ x) {
    extern __shared__ char smem[];
    uint32_t sb = smem_u32(smem);
    int tid = threadIdx.x;
    int lane = tid & 31, warp = tid >> 5;
    int m0 = warp * 16;
    int row0 = blockIdx.x * TM;

    // A: x rows -> fp16 of (-2x), padded, aug col 64 = 1.0
    #pragma unroll
    for (int i = 0; i < 8; i++) {
        int f = tid + i * 256;          // 2048 float4 = 128 rows x 16
        int row = f >> 4, j = f & 15;
        float4 v = *(const float4*)(x + (row0 + row) * D + 4 * j);
        __half h0 = __float2half(-2.0f * v.x), h1 = __float2half(-2.0f * v.y);
        __half h2 = __float2half(-2.0f * v.z), h3 = __float2half(-2.0f * v.w);
        *(uint2*)(smem + S_A + (uint32_t)row * ROWB + j * 8) = make_uint2(
            (uint32_t)__half_as_ushort(h0) | ((uint32_t)__half_as_ushort(h1) << 16),
            (uint32_t)__half_as_ushort(h2) | ((uint32_t)__half_as_ushort(h3) << 16));
    }
    if (tid < 128) {
        uint32_t base = S_A + (uint32_t)tid * ROWB + 128;   // byte offset of col 64
        *(uint4*)(smem + base)      = make_uint4(0x3C00u, 0u, 0u, 0u);   // 1.0h, zeros
        *(uint4*)(smem + base + 16) = make_uint4(0u, 0u, 0u, 0u);
        *(uint4*)(smem + base + 32) = make_uint4(0u, 0u, 0u, 0u);
    }

    auto loadB = [&](int chunk) {
        uint32_t dst = sb + S_B + (uint32_t)(chunk & 1) * PLANE;
        const char* src = (const char*)(d_Bh + chunk * 64 * KPAD);
        #pragma unroll
        for (int i = 0; i < 3; i++) {
            int u = tid + i * 256;                 // 704 16B units
            if (u < 704) cp_async16(dst + 16 * u, src + 16 * u);
        }
        cp_commit();
    };

    loadB(0);
    cp_wait0();
    __syncthreads();

    int r = lane & 7, q = lane >> 3;
    uint32_t aAddr = sb + S_A + (uint32_t)(m0 + r + ((q & 1) << 3)) * ROWB + ((q >> 1) << 4);
    uint32_t bOff = (uint32_t)(r + ((q >> 1) << 3)) * ROWB + ((q & 1) << 4);

    uint32_t ah[5][4];
    #pragma unroll
    for (int k = 0; k < 5; k++) ldm_x4(ah[k], aAddr + k * 32);

    float bA = 3.4e38f, b2A = 3.4e38f, bB = 3.4e38f, b2B = 3.4e38f;
    int iA = 0, iB = 0;

    #pragma unroll 1
    for (int c = 0; c < 16; c++) {
        if (c < 15) loadB(c + 1);     // async prefetch into other buffer

        uint32_t bbase = sb + S_B + (uint32_t)(c & 1) * PLANE + bOff;

        float acc[8][4];
        #pragma unroll
        for (int nb = 0; nb < 8; nb++)
            #pragma unroll
            for (int j = 0; j < 4; j++) acc[nb][j] = 0.0f;

        #pragma unroll
        for (int k = 0; k < 5; k++) {
            #pragma unroll
            for (int t = 0; t < 4; t++) {
                uint32_t bh[4];
                ldm_x4(bh, bbase + t * (16 * ROWB) + k * 32);
                mma_f16(acc[2*t],   ah[k], bh);
                mma_f16(acc[2*t+1], ah[k], bh + 2);
            }
        }

        int kbase = c * 64 + 2 * (lane & 3);
        #pragma unroll
        for (int nb = 0; nb < 8; nb++) {
            #pragma unroll
            for (int j = 0; j < 4; j++) {
                float v = acc[nb][j];
                int kidx = kbase + nb * 8 + (j & 1);
                if (j < 2) {
                    if (v < bA) { b2A = bA; bA = v; iA = kidx; } else b2A = fminf(b2A, v);
                } else {
                    if (v < bB) { b2B = bB; bB = v; iB = kidx; } else b2B = fminf(b2B, v);
                }
            }
        }
        cp_wait0();
        __syncthreads();
    }

    #pragma unroll
    for (int off = 1; off <= 2; off <<= 1) {
        float ov = __shfl_xor_sync(0xffffffff, bA, off);
        float ov2 = __shfl_xor_sync(0xffffffff, b2A, off);
        int   oi = __shfl_xor_sync(0xffffffff, iA, off);
        if (ov < bA) { b2A = fminf(bA, ov2); bA = ov; iA = oi; } else b2A = fminf(b2A, ov);
        ov = __shfl_xor_sync(0xffffffff, bB, off);
        ov2 = __shfl_xor_sync(0xffffffff, b2B, off);
        oi = __shfl_xor_sync(0xffffffff, iB, off);
        if (ov < bB) { b2B = fminf(bB, ov2); bB = ov; iB = oi; } else b2B = fminf(b2B, ov);
    }
    if ((lane & 3) == 0) {
        int rowA = row0 + m0 + (lane >> 2);
        d_idx[rowA] = iA;
        if (b2A - bA < MARGIN_COARSE) { int p = atomicAdd(&d_flagCnt, 1); d_flagList[p] = rowA; }
        int rowB = rowA + 8;
        d_idx[rowB] = iB;
        if (b2B - bB < MARGIN_COARSE) { int p = atomicAdd(&d_flagCnt, 1); d_flagList[p] = rowB; }
    }
}

// ---------------- Kernel E (idx 4): exact float-float resolve, COALESCED ----------------
// Thread tid handles codes {tid, tid+256, tid+512, tid+768}; reads emb in its native
// [d][K] layout so warp lanes hit consecutive addresses (1 wavefront per load, was 32).
// Math identical to the validated path: sim in float-float on the FMA pipe, then the
// reference's fp32 op sequence: dist = fl32( fl32(xn + en_k) - fl32(2*sim) ).
__global__ __launch_bounds__(256, 1)
void exact_kernel(const float* __restrict__ x, const float* __restrict__ emb) {
    __shared__ float sx[D];
    __shared__ float sxn;
    __shared__ float rv[256];
    __shared__ int   ri[256];
    int tid = threadIdx.x;

    int cnt = d_flagCnt;
    for (int i = blockIdx.x; i < cnt; i += gridDim.x) {
        int row = d_flagList[i];
        if (tid < D / 4) {
            float4 v = *(const float4*)(x + row * D + 4 * tid);
            sx[4*tid] = v.x; sx[4*tid+1] = v.y; sx[4*tid+2] = v.z; sx[4*tid+3] = v.w;
        }
        __syncthreads();
        if (tid == 0) {
            float a = 0.0f;
            for (int dd = 0; dd < D; dd++)
                a = __fadd_rn(a, __fmul_rn(sx[dd], sx[dd]));   // ref-style norm
            sxn = a;
        }
        __syncthreads();
        float xn = sxn;

        float s0 = 0.f, c0 = 0.f, s1 = 0.f, c1 = 0.f;
        float s2 = 0.f, c2 = 0.f, s3 = 0.f, c3 = 0.f;
        #pragma unroll 4
        for (int dd = 0; dd < D; dd++) {
            float xv = sx[dd];
            const float* er = emb + dd * K + tid;   // coalesced across lanes
            ddAccum(s0, c0, xv, er[0]);
            ddAccum(s1, c1, xv, er[256]);
            ddAccum(s2, c2, xv, er[512]);
            ddAccum(s3, c3, xv, er[768]);
        }
        float ss[4] = {s0, s1, s2, s3};
        float cc[4] = {c0, c1, c2, c3};
        float bv = 3.4e38f; int bi = 0;
        #pragma unroll
        for (int t = 0; t < 4; t++) {
            int k = tid + 256 * t;                  // ascending within thread
            float hi, lo;
            twoSum(ss[t], cc[t], hi, lo);
            float s2f = __fmaf_rn(2.0f, lo, __fmul_rn(2.0f, hi));   // fl32(2*sim)
            float t1 = __fadd_rn(xn, d_en[k]);
            float dist = __fsub_rn(t1, s2f);
            if (dist < bv) { bv = dist; bi = k; }   // strict <: first index within thread
        }
        rv[tid] = bv; ri[tid] = bi;
        __syncthreads();
        for (int off = 128; off > 0; off >>= 1) {
            if (tid < off) {
                float ov = rv[tid + off]; int oi = ri[tid + off];
                if (ov < rv[tid] || (ov == rv[tid] && oi < ri[tid])) {
                    rv[tid] = ov; ri[tid] = oi;
                }
            }
            __syncthreads();
        }
        if (tid == 0) d_idx[row] = ri[0];
        __syncthreads();
    }
}

// ---------------- Kernel F (idx 5): gather + straight-through + loss ----------------
__global__ void out_kernel(const float* __restrict__ x, float* __restrict__ out) {
    int t = blockIdx.x * blockDim.x + threadIdx.x;   // float4 index
    int r = t >> 4, j = t & 15;
    int idx = d_idx[r];
    float4 xv = ((const float4*)x)[t];
    float4 qv = *(const float4*)(d_eT + idx * D + 4 * j);
    float dx = qv.x - xv.x, dy = qv.y - xv.y, dz = qv.z - xv.z, dw = qv.w - xv.w;
    ((float4*)out)[t] = make_float4(xv.x + dx, xv.y + dy, xv.z + dz, xv.w + dw);
    float v = dx * dx + dy * dy + dz * dz + dw * dw;

    #pragma unroll
    for (int off = 16; off > 0; off >>= 1) v += __shfl_xor_sync(0xffffffff, v, off);
    __shared__ float ws[8];
    int wid = threadIdx.x >> 5, lid = threadIdx.x & 31;
    if (lid == 0) ws[wid] = v;
    __syncthreads();
    if (threadIdx.x == 0) {
        float s = 0.0f;
        #pragma unroll
        for (int i = 0; i < 8; i++) s += ws[i];
        atomicAdd(&d_lossAcc, s);
    }
}

// ---------------- Kernel G (idx 6): finalize loss ----------------
__global__ void fin_kernel(float* __restrict__ out, int out_size) {
    out[out_size - 1] = 1.25f * d_lossAcc * (1.0f / (float)(N_ROWS * D));
}

extern "C" void kernel_launch(void* const* d_in, const int* in_sizes, int n_in,
                              void* d_out, int out_size) {
    const float* x   = (const float*)d_in[0];
    const float* emb = (const float*)d_in[1];
    float* out = (float*)d_out;

    prep1_kernel<<<4, 256>>>(emb);                       // idx 0
    prep2_kernel<<<4, 256>>>();                          // idx 1
    prep3_kernel<<<1, 1>>>();                            // idx 2
    gemm_argmin_kernel<<<N_ROWS / TM, 256, S_TOTAL>>>(x);// idx 3  (profiled)
    exact_kernel<<<512, 256>>>(x, emb);                  // idx 4
    out_kernel<<<(N_ROWS * D / 4) / 256, 256>>>(x, out); // idx 5
    fin_kernel<<<1, 1>>>(out, out_size);                 // idx 6
}

// round 8
// speedup vs baseline: 4.0843x; 1.0264x over previous
#include <cuda_runtime.h>
#include <cuda_fp16.h>
#include <cstdint>

#define N_ROWS 32768
#define D 64
#define K 1024
#define KPAD 88            // padded k-extent in halfs; row stride 176 B (conflict-free ldmatrix)
#define ROWB 176
#define TM 128             // rows per CTA
#define NCH 32             // codes per B chunk (16 accumulator regs)
#define MARGIN_COARSE 4e-3f

__device__ float d_en[K];                        // fp32 ||e_k||^2 (ref-style mul-then-add)
__device__ float d_eT[K * D];                    // [k][d] fp32 (gather)
__device__ __align__(16) __half d_Bh[K * KPAD];  // [k][KPAD] fp16 codebook (+aug en at col 64)
__device__ int   d_idx[N_ROWS];
__device__ float d_lossAcc;
__device__ int   d_flagCnt;
__device__ int   d_flagList[N_ROWS];

// ---------------- helpers ----------------
__device__ __forceinline__ uint32_t smem_u32(const void* p) {
    uint32_t a;
    asm("{ .reg .u64 t; cvta.to.shared.u64 t, %1; cvt.u32.u64 %0, t; }" : "=r"(a) : "l"(p));
    return a;
}
__device__ __forceinline__ void ldm_x4(uint32_t* r, uint32_t addr) {
    asm volatile("ldmatrix.sync.aligned.m8n8.x4.shared.b16 {%0,%1,%2,%3}, [%4];"
        : "=r"(r[0]), "=r"(r[1]), "=r"(r[2]), "=r"(r[3]) : "r"(addr));
}
__device__ __forceinline__ void mma_f16(float* d, const uint32_t* a, const uint32_t* b) {
    asm volatile("mma.sync.aligned.m16n8k16.row.col.f32.f16.f16.f32 "
        "{%0,%1,%2,%3}, {%4,%5,%6,%7}, {%8,%9}, {%0,%1,%2,%3};"
        : "+f"(d[0]), "+f"(d[1]), "+f"(d[2]), "+f"(d[3])
        : "r"(a[0]), "r"(a[1]), "r"(a[2]), "r"(a[3]), "r"(b[0]), "r"(b[1]));
}
__device__ __forceinline__ void cp_async16(uint32_t sdst, const void* gsrc) {
    asm volatile("cp.async.cg.shared.global [%0], [%1], 16;" :: "r"(sdst), "l"(gsrc) : "memory");
}
__device__ __forceinline__ void cp_commit() { asm volatile("cp.async.commit_group;" ::: "memory"); }
__device__ __forceinline__ void cp_wait0()  { asm volatile("cp.async.wait_group 0;" ::: "memory"); }

// float-float (double-single) primitives — full-rate FMA pipe
__device__ __forceinline__ void twoSum(float a, float b, float& s, float& e) {
    s = __fadd_rn(a, b);
    float bb = __fsub_rn(s, a);
    e = __fadd_rn(__fsub_rn(a, __fsub_rn(s, bb)), __fsub_rn(b, bb));
}
__device__ __forceinline__ void ddAccum(float& s, float& c, float x, float e) {
    float p = __fmul_rn(x, e);
    float perr = __fmaf_rn(x, e, -p);
    float t, err;
    twoSum(s, p, t, err);
    s = t;
    c = __fadd_rn(c, __fadd_rn(err, perr));
}

// ---------------- Kernel 0: fused prep ----------------
// Norms (ref-style mul-then-add), transpose to [k][d], fp16 pack + aug col, zero accs.
__global__ void prep_kernel(const float* __restrict__ emb) {
    int k = blockIdx.x * blockDim.x + threadIdx.x;
    if (k == 0) { d_lossAcc = 0.0f; d_flagCnt = 0; }
    if (k < K) {
        float s = 0.0f;
        float fbuf[4];
        for (int dd = 0; dd < D; dd += 4) {
            #pragma unroll
            for (int u = 0; u < 4; u++) {
                float v = emb[(dd + u) * K + k];            // coalesced across lanes
                s = __fadd_rn(s, __fmul_rn(v, v));          // ref-style mul-then-add
                fbuf[u] = v;
            }
            *(float4*)(d_eT + k * D + dd) = make_float4(fbuf[0], fbuf[1], fbuf[2], fbuf[3]);
            __half h0 = __float2half(fbuf[0]), h1 = __float2half(fbuf[1]);
            __half h2 = __float2half(fbuf[2]), h3 = __float2half(fbuf[3]);
            *(uint2*)(d_Bh + k * KPAD + dd) = make_uint2(
                (uint32_t)__half_as_ushort(h0) | ((uint32_t)__half_as_ushort(h1) << 16),
                (uint32_t)__half_as_ushort(h2) | ((uint32_t)__half_as_ushort(h3) << 16));
        }
        d_en[k] = s;
        *(uint2*)(d_Bh + k * KPAD + 64) = make_uint2((uint32_t)__half_as_ushort(__float2half(s)), 0u);
        *(uint2*)(d_Bh + k * KPAD + 68) = make_uint2(0u, 0u);
        *(uint4*)(d_Bh + k * KPAD + 72) = make_uint4(0u, 0u, 0u, 0u);
        *(uint4*)(d_Bh + k * KPAD + 80) = make_uint4(0u, 0u, 0u, 0u);
    }
}

// ---------------- Kernel 1: fp16 HMMA coarse + fused argmin ----------------
// smem: A[128][88]h = 22528 B, B double buffer 2 x [32][88]h = 2 x 5632 B
#define S_A   0
#define S_B   22528
#define PLANE 5632
#define S_TOTAL 33792

__global__ __launch_bounds__(256, 3)
void gemm_argmin_kernel(const float* __restrict__ x) {
    extern __shared__ char smem[];
    uint32_t sb = smem_u32(smem);
    int tid = threadIdx.x;
    int lane = tid & 31, warp = tid >> 5;
    int m0 = warp * 16;
    int row0 = blockIdx.x * TM;

    // A: x rows -> fp16 of (-2x), padded, aug col 64 = 1.0
    #pragma unroll
    for (int i = 0; i < 8; i++) {
        int f = tid + i * 256;          // 2048 float4 = 128 rows x 16
        int row = f >> 4, j = f & 15;
        float4 v = *(const float4*)(x + (row0 + row) * D + 4 * j);
        __half h0 = __float2half(-2.0f * v.x), h1 = __float2half(-2.0f * v.y);
        __half h2 = __float2half(-2.0f * v.z), h3 = __float2half(-2.0f * v.w);
        *(uint2*)(smem + S_A + (uint32_t)row * ROWB + j * 8) = make_uint2(
            (uint32_t)__half_as_ushort(h0) | ((uint32_t)__half_as_ushort(h1) << 16),
            (uint32_t)__half_as_ushort(h2) | ((uint32_t)__half_as_ushort(h3) << 16));
    }
    if (tid < 128) {
        uint32_t base = S_A + (uint32_t)tid * ROWB + 128;   // byte offset of col 64
        *(uint4*)(smem + base)      = make_uint4(0x3C00u, 0u, 0u, 0u);   // 1.0h, zeros
        *(uint4*)(smem + base + 16) = make_uint4(0u, 0u, 0u, 0u);
        *(uint4*)(smem + base + 32) = make_uint4(0u, 0u, 0u, 0u);
    }

    // B chunk = 32 codes x 176 B = 352 16B units
    auto loadB = [&](int chunk) {
        uint32_t dst = sb + S_B + (uint32_t)(chunk & 1) * PLANE;
        const char* src = (const char*)(d_Bh + chunk * NCH * KPAD);
        if (tid < 96)  cp_async16(dst + 16 * tid,        src + 16 * tid);
        int u = tid + 96;
        if (u < 352)   cp_async16(dst + 16 * u,          src + 16 * u);
        cp_commit();
    };

    loadB(0);
    cp_wait0();
    __syncthreads();

    int r = lane & 7, q = lane >> 3;
    uint32_t aAddr = sb + S_A + (uint32_t)(m0 + r + ((q & 1) << 3)) * ROWB + ((q >> 1) << 4);
    uint32_t bOff = (uint32_t)(r + ((q >> 1) << 3)) * ROWB + ((q & 1) << 4);

    uint32_t ah[5][4];
    #pragma unroll
    for (int k = 0; k < 5; k++) ldm_x4(ah[k], aAddr + k * 32);

    float bA = 3.4e38f, b2A = 3.4e38f, bB = 3.4e38f, b2B = 3.4e38f;
    int iA = 0, iB = 0;

    #pragma unroll 1
    for (int c = 0; c < K / NCH; c++) {
        if (c < K / NCH - 1) loadB(c + 1);     // async prefetch into other buffer

        uint32_t bbase = sb + S_B + (uint32_t)(c & 1) * PLANE + bOff;

        float acc[4][4];
        #pragma unroll
        for (int nb = 0; nb < 4; nb++)
            #pragma unroll
            for (int j = 0; j < 4; j++) acc[nb][j] = 0.0f;

        #pragma unroll
        for (int k = 0; k < 5; k++) {
            #pragma unroll
            for (int t = 0; t < 2; t++) {
                uint32_t bh[4];
                ldm_x4(bh, bbase + t * (16 * ROWB) + k * 32);
                mma_f16(acc[2*t],   ah[k], bh);
                mma_f16(acc[2*t+1], ah[k], bh + 2);
            }
        }

        int kbase = c * NCH + 2 * (lane & 3);
        #pragma unroll
        for (int nb = 0; nb < 4; nb++) {
            #pragma unroll
            for (int j = 0; j < 4; j++) {
                float v = acc[nb][j];
                int kidx = kbase + nb * 8 + (j & 1);
                if (j < 2) {
                    if (v < bA) { b2A = bA; bA = v; iA = kidx; } else b2A = fminf(b2A, v);
                } else {
                    if (v < bB) { b2B = bB; bB = v; iB = kidx; } else b2B = fminf(b2B, v);
                }
            }
        }
        cp_wait0();
        __syncthreads();
    }

    #pragma unroll
    for (int off = 1; off <= 2; off <<= 1) {
        float ov = __shfl_xor_sync(0xffffffff, bA, off);
        float ov2 = __shfl_xor_sync(0xffffffff, b2A, off);
        int   oi = __shfl_xor_sync(0xffffffff, iA, off);
        if (ov < bA) { b2A = fminf(bA, ov2); bA = ov; iA = oi; } else b2A = fminf(b2A, ov);
        ov = __shfl_xor_sync(0xffffffff, bB, off);
        ov2 = __shfl_xor_sync(0xffffffff, b2B, off);
        oi = __shfl_xor_sync(0xffffffff, iB, off);
        if (ov < bB) { b2B = fminf(bB, ov2); bB = ov; iB = oi; } else b2B = fminf(b2B, ov);
    }
    if ((lane & 3) == 0) {
        int rowA = row0 + m0 + (lane >> 2);
        d_idx[rowA] = iA;
        if (b2A - bA < MARGIN_COARSE) { int p = atomicAdd(&d_flagCnt, 1); d_flagList[p] = rowA; }
        int rowB = rowA + 8;
        d_idx[rowB] = iB;
        if (b2B - bB < MARGIN_COARSE) { int p = atomicAdd(&d_flagCnt, 1); d_flagList[p] = rowB; }
    }
}

// ---------------- Kernel 2: exact float-float resolve, coalesced ----------------
__global__ __launch_bounds__(256, 1)
void exact_kernel(const float* __restrict__ x, const float* __restrict__ emb) {
    __shared__ float sx[D];
    __shared__ float sxn;
    __shared__ float rv[256];
    __shared__ int   ri[256];
    int tid = threadIdx.x;

    int cnt = d_flagCnt;
    for (int i = blockIdx.x; i < cnt; i += gridDim.x) {
        int row = d_flagList[i];
        if (tid < D / 4) {
            float4 v = *(const float4*)(x + row * D + 4 * tid);
            sx[4*tid] = v.x; sx[4*tid+1] = v.y; sx[4*tid+2] = v.z; sx[4*tid+3] = v.w;
        }
        __syncthreads();
        if (tid == 0) {
            float a = 0.0f;
            for (int dd = 0; dd < D; dd++)
                a = __fadd_rn(a, __fmul_rn(sx[dd], sx[dd]));   // ref-style norm
            sxn = a;
        }
        __syncthreads();
        float xn = sxn;

        float s0 = 0.f, c0 = 0.f, s1 = 0.f, c1 = 0.f;
        float s2 = 0.f, c2 = 0.f, s3 = 0.f, c3 = 0.f;
        #pragma unroll 4
        for (int dd = 0; dd < D; dd++) {
            float xv = sx[dd];
            const float* er = emb + dd * K + tid;   // coalesced across lanes
            ddAccum(s0, c0, xv, er[0]);
            ddAccum(s1, c1, xv, er[256]);
            ddAccum(s2, c2, xv, er[512]);
            ddAccum(s3, c3, xv, er[768]);
        }
        float ss[4] = {s0, s1, s2, s3};
        float cc[4] = {c0, c1, c2, c3};
        float bv = 3.4e38f; int bi = 0;
        #pragma unroll
        for (int t = 0; t < 4; t++) {
            int k = tid + 256 * t;                  // ascending within thread
            float hi, lo;
            twoSum(ss[t], cc[t], hi, lo);
            float s2f = __fmaf_rn(2.0f, lo, __fmul_rn(2.0f, hi));   // fl32(2*sim)
            float t1 = __fadd_rn(xn, d_en[k]);
            float dist = __fsub_rn(t1, s2f);
            if (dist < bv) { bv = dist; bi = k; }
        }
        rv[tid] = bv; ri[tid] = bi;
        __syncthreads();
        for (int off = 128; off > 0; off >>= 1) {
            if (tid < off) {
                float ov = rv[tid + off]; int oi = ri[tid + off];
                if (ov < rv[tid] || (ov == rv[tid] && oi < ri[tid])) {
                    rv[tid] = ov; ri[tid] = oi;
                }
            }
            __syncthreads();
        }
        if (tid == 0) d_idx[row] = ri[0];
        __syncthreads();
    }
}

// ---------------- Kernel 3 (profiled idx 3): gather + straight-through + loss, 4x ILP ----------------
#define OUT_T (N_ROWS * D / 4)       // 524288 float4
#define OUT_STRIDE (OUT_T / 4)       // 131072 threads, 4 float4 each
__global__ void out_kernel(const float* __restrict__ x, float* __restrict__ out) {
    int t0 = blockIdx.x * blockDim.x + threadIdx.x;
    float v = 0.0f;
    #pragma unroll
    for (int i = 0; i < 4; i++) {
        int t = t0 + i * OUT_STRIDE;
        int r = t >> 4, j = t & 15;
        int idx = d_idx[r];
        float4 xv = ((const float4*)x)[t];
        float4 qv = *(const float4*)(d_eT + idx * D + 4 * j);
        float dx = qv.x - xv.x, dy = qv.y - xv.y, dz = qv.z - xv.z, dw = qv.w - xv.w;
        ((float4*)out)[t] = make_float4(xv.x + dx, xv.y + dy, xv.z + dz, xv.w + dw);
        v += dx * dx + dy * dy + dz * dz + dw * dw;
    }

    #pragma unroll
    for (int off = 16; off > 0; off >>= 1) v += __shfl_xor_sync(0xffffffff, v, off);
    __shared__ float ws[8];
    int wid = threadIdx.x >> 5, lid = threadIdx.x & 31;
    if (lid == 0) ws[wid] = v;
    __syncthreads();
    if (threadIdx.x == 0) {
        float s = 0.0f;
        #pragma unroll
        for (int i = 0; i < 8; i++) s += ws[i];
        atomicAdd(&d_lossAcc, s);
    }
}

// ---------------- Kernel 4: finalize loss ----------------
__global__ void fin_kernel(float* __restrict__ out, int out_size) {
    out[out_size - 1] = 1.25f * d_lossAcc * (1.0f / (float)(N_ROWS * D));
}

extern "C" void kernel_launch(void* const* d_in, const int* in_sizes, int n_in,
                              void* d_out, int out_size) {
    const float* x   = (const float*)d_in[0];
    const float* emb = (const float*)d_in[1];
    float* out = (float*)d_out;

    prep_kernel<<<4, 256>>>(emb);                        // idx 0
    gemm_argmin_kernel<<<N_ROWS / TM, 256, S_TOTAL>>>(x);// idx 1
    exact_kernel<<<512, 256>>>(x, emb);                  // idx 2
    out_kernel<<<OUT_STRIDE / 256, 256>>>(x, out);       // idx 3  (profiled)
    fin_kernel<<<1, 1>>>(out, out_size);                 // idx 4
}

// round 9
// speedup vs baseline: 5.0687x; 1.2410x over previous
#include <cuda_runtime.h>
#include <cuda_fp16.h>
#include <cstdint>

#define N_ROWS 32768
#define D 64
#define K 1024
#define KPAD 88            // padded k-extent in halfs; row stride 176 B (conflict-free ldmatrix)
#define ROWB 176
#define TM 128             // rows per CTA
#define NCH 32             // codes per chunk
#define MARGIN_COARSE 2e-3f

__device__ float d_en[K];                        // fp32 ||e_k||^2 (ref-style mul-then-add)
__device__ float d_eT[K * D];                    // [k][d] fp32 (gather)
__device__ __align__(16) __half d_Bh[K * KPAD];  // [k][KPAD] fp16 codebook (+aug en at col 64)
__device__ int   d_idx[N_ROWS];
__device__ float d_lossAcc;
__device__ int   d_flagCnt;
__device__ int   d_flagList[N_ROWS];

// ---------------- helpers ----------------
__device__ __forceinline__ uint32_t smem_u32(const void* p) {
    uint32_t a;
    asm("{ .reg .u64 t; cvta.to.shared.u64 t, %1; cvt.u32.u64 %0, t; }" : "=r"(a) : "l"(p));
    return a;
}
__device__ __forceinline__ void ldm_x4(uint32_t* r, uint32_t addr) {
    asm volatile("ldmatrix.sync.aligned.m8n8.x4.shared.b16 {%0,%1,%2,%3}, [%4];"
        : "=r"(r[0]), "=r"(r[1]), "=r"(r[2]), "=r"(r[3]) : "r"(addr));
}
__device__ __forceinline__ void mma_f16(float* d, const uint32_t* a, const uint32_t* b) {
    asm volatile("mma.sync.aligned.m16n8k16.row.col.f32.f16.f16.f32 "
        "{%0,%1,%2,%3}, {%4,%5,%6,%7}, {%8,%9}, {%0,%1,%2,%3};"
        : "+f"(d[0]), "+f"(d[1]), "+f"(d[2]), "+f"(d[3])
        : "r"(a[0]), "r"(a[1]), "r"(a[2]), "r"(a[3]), "r"(b[0]), "r"(b[1]));
}
__device__ __forceinline__ void cp_async16(uint32_t sdst, const void* gsrc) {
    asm volatile("cp.async.cg.shared.global [%0], [%1], 16;" :: "r"(sdst), "l"(gsrc) : "memory");
}
__device__ __forceinline__ void cp_commit() { asm volatile("cp.async.commit_group;" ::: "memory"); }
__device__ __forceinline__ void cp_wait0()  { asm volatile("cp.async.wait_group 0;" ::: "memory"); }

// float-float (double-single) primitives — full-rate FMA pipe
__device__ __forceinline__ void twoSum(float a, float b, float& s, float& e) {
    s = __fadd_rn(a, b);
    float bb = __fsub_rn(s, a);
    e = __fadd_rn(__fsub_rn(a, __fsub_rn(s, bb)), __fsub_rn(b, bb));
}
__device__ __forceinline__ void ddAccum(float& s, float& c, float x, float e) {
    float p = __fmul_rn(x, e);
    float perr = __fmaf_rn(x, e, -p);
    float t, err;
    twoSum(s, p, t, err);
    s = t;
    c = __fadd_rn(c, __fadd_rn(err, perr));
}

// ---------------- Kernel A (idx 0): norms + transpose ----------------
__global__ void prep1_kernel(const float* __restrict__ emb) {
    int k = blockIdx.x * blockDim.x + threadIdx.x;
    if (k < K) {
        float s = 0.0f;
        float fbuf[4];
        for (int dd = 0; dd < D; dd += 4) {
            #pragma unroll
            for (int u = 0; u < 4; u++) {
                float v = emb[(dd + u) * K + k];            // coalesced across lanes
                s = __fadd_rn(s, __fmul_rn(v, v));          // ref-style mul-then-add
                fbuf[u] = v;
            }
            *(float4*)(d_eT + k * D + dd) = make_float4(fbuf[0], fbuf[1], fbuf[2], fbuf[3]);
        }
        d_en[k] = s;
    }
}

// ---------------- Kernel B (idx 1): fp16 pack + aug column ----------------
__global__ void prep2_kernel() {
    int k = blockIdx.x * blockDim.x + threadIdx.x;
    if (k < K) {
        float s = d_en[k];
        for (int dd = 0; dd < D; dd += 4) {
            float4 v = *(const float4*)(d_eT + k * D + dd);
            __half h0 = __float2half(v.x), h1 = __float2half(v.y);
            __half h2 = __float2half(v.z), h3 = __float2half(v.w);
            *(uint2*)(d_Bh + k * KPAD + dd) = make_uint2(
                (uint32_t)__half_as_ushort(h0) | ((uint32_t)__half_as_ushort(h1) << 16),
                (uint32_t)__half_as_ushort(h2) | ((uint32_t)__half_as_ushort(h3) << 16));
        }
        *(uint2*)(d_Bh + k * KPAD + 64) = make_uint2((uint32_t)__half_as_ushort(__float2half(s)), 0u);
        *(uint2*)(d_Bh + k * KPAD + 68) = make_uint2(0u, 0u);
        *(uint4*)(d_Bh + k * KPAD + 72) = make_uint4(0u, 0u, 0u, 0u);
        *(uint4*)(d_Bh + k * KPAD + 80) = make_uint4(0u, 0u, 0u, 0u);
    }
}

// ---------------- Kernel C (idx 2): zero accumulators ----------------
__global__ void prep3_kernel() {
    d_lossAcc = 0.0f;
    d_flagCnt = 0;
}

// ---------------- Kernel D (idx 3, PROFILED): fp16 HMMA coarse + fused argmin ----------------
// 512 threads / 16 warps: warp w -> row group (w&7)*16, chunk parity (w>>3).
// smem: A[128][88]h = 22528 B; B 4 planes of [32][88]h = 4 x 5632 (pair double-buffer)
#define S_A   0
#define S_B   22528
#define PLANE 5632
#define S_TOTAL 45056

__global__ __launch_bounds__(512, 2)
void gemm_argmin_kernel(const float* __restrict__ x) {
    extern __shared__ char smem[];
    uint32_t sb = smem_u32(smem);
    int tid = threadIdx.x;
    int lane = tid & 31, warp = tid >> 5;
    int par = warp >> 3;                  // 0: even chunks, 1: odd chunks
    int m0 = (warp & 7) * 16;             // row group
    int row0 = blockIdx.x * TM;

    // A: x rows -> fp16 of (-2x), padded, aug col 64 = 1.0
    #pragma unroll
    for (int i = 0; i < 4; i++) {
        int f = tid + i * 512;          // 2048 float4 = 128 rows x 16
        int row = f >> 4, j = f & 15;
        float4 v = *(const float4*)(x + (row0 + row) * D + 4 * j);
        __half h0 = __float2half(-2.0f * v.x), h1 = __float2half(-2.0f * v.y);
        __half h2 = __float2half(-2.0f * v.z), h3 = __float2half(-2.0f * v.w);
        *(uint2*)(smem + S_A + (uint32_t)row * ROWB + j * 8) = make_uint2(
            (uint32_t)__half_as_ushort(h0) | ((uint32_t)__half_as_ushort(h1) << 16),
            (uint32_t)__half_as_ushort(h2) | ((uint32_t)__half_as_ushort(h3) << 16));
    }
    if (tid < 128) {
        uint32_t base = S_A + (uint32_t)tid * ROWB + 128;   // byte offset of col 64
        *(uint4*)(smem + base)      = make_uint4(0x3C00u, 0u, 0u, 0u);   // 1.0h, zeros
        *(uint4*)(smem + base + 16) = make_uint4(0u, 0u, 0u, 0u);
        *(uint4*)(smem + base + 32) = make_uint4(0u, 0u, 0u, 0u);
    }

    // load chunk PAIR 2p, 2p+1 (contiguous 704 16B units) into buffer p&1
    auto loadBpair = [&](int p) {
        uint32_t dst = sb + S_B + (uint32_t)(p & 1) * (2 * PLANE);
        const char* src = (const char*)(d_Bh + p * 2 * NCH * KPAD);
        cp_async16(dst + 16 * tid, src + 16 * tid);
        int u = tid + 512;
        if (u < 704) cp_async16(dst + 16 * u, src + 16 * u);
        cp_commit();
    };

    loadBpair(0);
    cp_wait0();
    __syncthreads();

    int r = lane & 7, q = lane >> 3;
    uint32_t aAddr = sb + S_A + (uint32_t)(m0 + r + ((q & 1) << 3)) * ROWB + ((q >> 1) << 4);
    uint32_t bOff = (uint32_t)(r + ((q >> 1) << 3)) * ROWB + ((q & 1) << 4);

    uint32_t ah[5][4];
    #pragma unroll
    for (int k = 0; k < 5; k++) ldm_x4(ah[k], aAddr + k * 32);

    float bA = 3.4e38f, b2A = 3.4e38f, bB = 3.4e38f, b2B = 3.4e38f;
    int iA = 0, iB = 0;

    #pragma unroll 1
    for (int c = 0; c < 16; c++) {        // 16 pairs; this warp does chunk 2c+par
        if (c < 15) loadBpair(c + 1);     // async prefetch into other buffer

        uint32_t bbase = sb + S_B + (uint32_t)(c & 1) * (2 * PLANE)
                       + (uint32_t)par * PLANE + bOff;

        float acc[4][4];
        #pragma unroll
        for (int nb = 0; nb < 4; nb++)
            #pragma unroll
            for (int j = 0; j < 4; j++) acc[nb][j] = 0.0f;

        #pragma unroll
        for (int k = 0; k < 5; k++) {
            #pragma unroll
            for (int t = 0; t < 2; t++) {
                uint32_t bh[4];
                ldm_x4(bh, bbase + t * (16 * ROWB) + k * 32);
                mma_f16(acc[2*t],   ah[k], bh);
                mma_f16(acc[2*t+1], ah[k], bh + 2);
            }
        }

        int kbase = (2 * c + par) * NCH + 2 * (lane & 3);
        #pragma unroll
        for (int nb = 0; nb < 4; nb++) {
            #pragma unroll
            for (int j = 0; j < 4; j++) {
                float v = acc[nb][j];
                int kidx = kbase + nb * 8 + (j & 1);
                if (j < 2) {
                    if (v < bA) { b2A = bA; bA = v; iA = kidx; } else b2A = fminf(b2A, v);
                } else {
                    if (v < bB) { b2B = bB; bB = v; iB = kidx; } else b2B = fminf(b2B, v);
                }
            }
        }
        cp_wait0();
        __syncthreads();
    }

    // lane-quad merge (4 lanes share each row)
    #pragma unroll
    for (int off = 1; off <= 2; off <<= 1) {
        float ov = __shfl_xor_sync(0xffffffff, bA, off);
        float ov2 = __shfl_xor_sync(0xffffffff, b2A, off);
        int   oi = __shfl_xor_sync(0xffffffff, iA, off);
        if (ov < bA) { b2A = fminf(bA, ov2); bA = ov; iA = oi; } else b2A = fminf(b2A, ov);
        ov = __shfl_xor_sync(0xffffffff, bB, off);
        ov2 = __shfl_xor_sync(0xffffffff, b2B, off);
        oi = __shfl_xor_sync(0xffffffff, iB, off);
        if (ov < bB) { b2B = fminf(bB, ov2); bB = ov; iB = oi; } else b2B = fminf(b2B, ov);
    }

    // cross-warp merge (par 0 vs par 1) via smem; exact-equal ties get flagged (gap 0)
    float* mv  = (float*)smem;            // reuse A region (fragments already in regs)
    float* mv2 = mv + 128;
    int*   mi  = (int*)(mv + 256);
    __syncthreads();
    if (par == 1 && (lane & 3) == 0) {
        int rA = m0 + (lane >> 2);
        mv[rA] = bA; mv2[rA] = b2A; mi[rA] = iA;
        int rB = rA + 8;
        mv[rB] = bB; mv2[rB] = b2B; mi[rB] = iB;
    }
    __syncthreads();
    if (par == 0 && (lane & 3) == 0) {
        int rA = m0 + (lane >> 2);
        {
            float ob = mv[rA], ob2 = mv2[rA]; int oi = mi[rA];
            float nb, nb2; int ni;
            if (ob < bA) { nb = ob; ni = oi; nb2 = fminf(bA, ob2); }
            else         { nb = bA; ni = iA; nb2 = fminf(b2A, ob); }
            int row = row0 + rA;
            d_idx[row] = ni;
            if (nb2 - nb < MARGIN_COARSE) { int p = atomicAdd(&d_flagCnt, 1); d_flagList[p] = row; }
        }
        int rB = rA + 8;
        {
            float ob = mv[rB], ob2 = mv2[rB]; int oi = mi[rB];
            float nb, nb2; int ni;
            if (ob < bB) { nb = ob; ni = oi; nb2 = fminf(bB, ob2); }
            else         { nb = bB; ni = iB; nb2 = fminf(b2B, ob); }
            int row = row0 + rB;
            d_idx[row] = ni;
            if (nb2 - nb < MARGIN_COARSE) { int p = atomicAdd(&d_flagCnt, 1); d_flagList[p] = row; }
        }
    }
}

// ---------------- Kernel E (idx 4): exact float-float resolve, coalesced ----------------
__global__ __launch_bounds__(256, 1)
void exact_kernel(const float* __restrict__ x, const float* __restrict__ emb) {
    __shared__ float sx[D];
    __shared__ float rv[256];
    __shared__ int   ri[256];
    int tid = threadIdx.x;

    int cnt = d_flagCnt;
    for (int i = blockIdx.x; i < cnt; i += gridDim.x) {
        int row = d_flagList[i];
        if (tid < D / 4) {
            float4 v = *(const float4*)(x + row * D + 4 * tid);
            sx[4*tid] = v.x; sx[4*tid+1] = v.y; sx[4*tid+2] = v.z; sx[4*tid+3] = v.w;
        }
        __syncthreads();

        // norm folded into main loop (same sequential fl32 order; identical in all threads)
        float sn = 0.0f;
        float s0 = 0.f, c0 = 0.f, s1 = 0.f, c1 = 0.f;
        float s2 = 0.f, c2 = 0.f, s3 = 0.f, c3 = 0.f;
        #pragma unroll 4
        for (int dd = 0; dd < D; dd++) {
            float xv = sx[dd];
            sn = __fadd_rn(sn, __fmul_rn(xv, xv));   // ref-style norm
            const float* er = emb + dd * K + tid;    // coalesced across lanes
            ddAccum(s0, c0, xv, er[0]);
            ddAccum(s1, c1, xv, er[256]);
            ddAccum(s2, c2, xv, er[512]);
            ddAccum(s3, c3, xv, er[768]);
        }
        float xn = sn;
        float ss[4] = {s0, s1, s2, s3};
        float cc[4] = {c0, c1, c2, c3};
        float bv = 3.4e38f; int bi = 0;
        #pragma unroll
        for (int t = 0; t < 4; t++) {
            int k = tid + 256 * t;                  // ascending within thread
            float hi, lo;
            twoSum(ss[t], cc[t], hi, lo);
            float s2f = __fmaf_rn(2.0f, lo, __fmul_rn(2.0f, hi));   // fl32(2*sim)
            float t1 = __fadd_rn(xn, d_en[k]);
            float dist = __fsub_rn(t1, s2f);
            if (dist < bv) { bv = dist; bi = k; }
        }
        rv[tid] = bv; ri[tid] = bi;
        __syncthreads();
        for (int off = 128; off > 0; off >>= 1) {
            if (tid < off) {
                float ov = rv[tid + off]; int oi = ri[tid + off];
                if (ov < rv[tid] || (ov == rv[tid] && oi < ri[tid])) {
                    rv[tid] = ov; ri[tid] = oi;
                }
            }
            __syncthreads();
        }
        if (tid == 0) d_idx[row] = ri[0];
        __syncthreads();
    }
}

// ---------------- Kernel F (idx 5): gather + straight-through + loss, 8x ILP ----------------
#define OUT_T (N_ROWS * D / 4)       // 524288 float4
#define OUT_STRIDE (OUT_T / 8)       // 65536 threads, 8 float4 each
__global__ void out_kernel(const float* __restrict__ x, float* __restrict__ out) {
    int t0 = blockIdx.x * blockDim.x + threadIdx.x;
    int idxs[8];
    #pragma unroll
    for (int i = 0; i < 8; i++) idxs[i] = d_idx[(t0 + i * OUT_STRIDE) >> 4];
    float v = 0.0f;
    #pragma unroll
    for (int i = 0; i < 8; i++) {
        int t = t0 + i * OUT_STRIDE;
        int j = t & 15;
        float4 xv = ((const float4*)x)[t];
        float4 qv = *(const float4*)(d_eT + idxs[i] * D + 4 * j);
        float dx = qv.x - xv.x, dy = qv.y - xv.y, dz = qv.z - xv.z, dw = qv.w - xv.w;
        ((float4*)out)[t] = make_float4(xv.x + dx, xv.y + dy, xv.z + dz, xv.w + dw);
        v += dx * dx + dy * dy + dz * dz + dw * dw;
    }

    #pragma unroll
    for (int off = 16; off > 0; off >>= 1) v += __shfl_xor_sync(0xffffffff, v, off);
    __shared__ float ws[8];
    int wid = threadIdx.x >> 5, lid = threadIdx.x & 31;
    if (lid == 0) ws[wid] = v;
    __syncthreads();
    if (threadIdx.x == 0) {
        float s = 0.0f;
        #pragma unroll
        for (int i = 0; i < 8; i++) s += ws[i];
        atomicAdd(&d_lossAcc, s);
    }
}

// ---------------- Kernel G (idx 6): finalize loss ----------------
__global__ void fin_kernel(float* __restrict__ out, int out_size) {
    out[out_size - 1] = 1.25f * d_lossAcc * (1.0f / (float)(N_ROWS * D));
}

extern "C" void kernel_launch(void* const* d_in, const int* in_sizes, int n_in,
                              void* d_out, int out_size) {
    const float* x   = (const float*)d_in[0];
    const float* emb = (const float*)d_in[1];
    float* out = (float*)d_out;

    prep1_kernel<<<4, 256>>>(emb);                        // idx 0
    prep2_kernel<<<4, 256>>>();                           // idx 1
    prep3_kernel<<<1, 1>>>();                             // idx 2
    gemm_argmin_kernel<<<N_ROWS / TM, 512, S_TOTAL>>>(x); // idx 3  (profiled)
    exact_kernel<<<512, 256>>>(x, emb);                   // idx 4
    out_kernel<<<OUT_STRIDE / 256, 256>>>(x, out);        // idx 5
    fin_kernel<<<1, 1>>>(out, out_size);                  // idx 6
}

// round 10
// speedup vs baseline: 6.0254x; 1.1887x over previous
#include <cuda_runtime.h>
#include <cuda_fp16.h>
#include <cstdint>

#define N_ROWS 32768
#define D 64
#define K 1024
#define KPAD 88            // padded k-extent in halfs; row stride 176 B (conflict-free ldmatrix)
#define ROWB 176
#define TM 128             // rows per CTA
#define NCH 32             // codes per chunk
#define MARGIN_COARSE 2e-3f

__device__ float d_en[K];                        // fp32 ||e_k||^2 (ref-style mul-then-add)
__device__ float d_eT[K * D];                    // [k][d] fp32 (gather)
__device__ __align__(16) __half d_Bh[K * KPAD];  // [k][KPAD] fp16 codebook (+aug en at col 64)
__device__ int   d_idx[N_ROWS];
__device__ float d_lossAcc;
__device__ int   d_flagCnt;
__device__ int   d_flagList[N_ROWS];
__device__ int   d_outDone;

// ---------------- helpers ----------------
__device__ __forceinline__ uint32_t smem_u32(const void* p) {
    uint32_t a;
    asm("{ .reg .u64 t; cvta.to.shared.u64 t, %1; cvt.u32.u64 %0, t; }" : "=r"(a) : "l"(p));
    return a;
}
__device__ __forceinline__ void ldm_x4(uint32_t* r, uint32_t addr) {
    asm volatile("ldmatrix.sync.aligned.m8n8.x4.shared.b16 {%0,%1,%2,%3}, [%4];"
        : "=r"(r[0]), "=r"(r[1]), "=r"(r[2]), "=r"(r[3]) : "r"(addr));
}
__device__ __forceinline__ void mma_f16(float* d, const uint32_t* a, const uint32_t* b) {
    asm volatile("mma.sync.aligned.m16n8k16.row.col.f32.f16.f16.f32 "
        "{%0,%1,%2,%3}, {%4,%5,%6,%7}, {%8,%9}, {%0,%1,%2,%3};"
        : "+f"(d[0]), "+f"(d[1]), "+f"(d[2]), "+f"(d[3])
        : "r"(a[0]), "r"(a[1]), "r"(a[2]), "r"(a[3]), "r"(b[0]), "r"(b[1]));
}
__device__ __forceinline__ void cp_async16(uint32_t sdst, const void* gsrc) {
    asm volatile("cp.async.cg.shared.global [%0], [%1], 16;" :: "r"(sdst), "l"(gsrc) : "memory");
}
__device__ __forceinline__ void cp_commit() { asm volatile("cp.async.commit_group;" ::: "memory"); }
__device__ __forceinline__ void cp_wait0()  { asm volatile("cp.async.wait_group 0;" ::: "memory"); }

// float-float (double-single) primitives — full-rate FMA pipe
__device__ __forceinline__ void twoSum(float a, float b, float& s, float& e) {
    s = __fadd_rn(a, b);
    float bb = __fsub_rn(s, a);
    e = __fadd_rn(__fsub_rn(a, __fsub_rn(s, bb)), __fsub_rn(b, bb));
}
__device__ __forceinline__ void ddAccum(float& s, float& c, float x, float e) {
    float p = __fmul_rn(x, e);
    float perr = __fmaf_rn(x, e, -p);
    float t, err;
    twoSum(s, p, t, err);
    s = t;
    c = __fadd_rn(c, __fadd_rn(err, perr));
}

// ---------------- Kernel 0: fused prep ----------------
__global__ void prep_kernel(const float* __restrict__ emb) {
    int k = blockIdx.x * blockDim.x + threadIdx.x;
    if (k == 0) { d_lossAcc = 0.0f; d_flagCnt = 0; d_outDone = 0; }
    if (k < K) {
        float s = 0.0f;
        float fbuf[4];
        #pragma unroll
        for (int dd = 0; dd < D; dd += 4) {
            #pragma unroll
            for (int u = 0; u < 4; u++) {
                float v = emb[(dd + u) * K + k];            // coalesced across lanes
                s = __fadd_rn(s, __fmul_rn(v, v));          // ref-style mul-then-add
                fbuf[u] = v;
            }
            *(float4*)(d_eT + k * D + dd) = make_float4(fbuf[0], fbuf[1], fbuf[2], fbuf[3]);
            __half h0 = __float2half(fbuf[0]), h1 = __float2half(fbuf[1]);
            __half h2 = __float2half(fbuf[2]), h3 = __float2half(fbuf[3]);
            *(uint2*)(d_Bh + k * KPAD + dd) = make_uint2(
                (uint32_t)__half_as_ushort(h0) | ((uint32_t)__half_as_ushort(h1) << 16),
                (uint32_t)__half_as_ushort(h2) | ((uint32_t)__half_as_ushort(h3) << 16));
        }
        d_en[k] = s;
        *(uint2*)(d_Bh + k * KPAD + 64) = make_uint2((uint32_t)__half_as_ushort(__float2half(s)), 0u);
        *(uint2*)(d_Bh + k * KPAD + 68) = make_uint2(0u, 0u);
        *(uint4*)(d_Bh + k * KPAD + 72) = make_uint4(0u, 0u, 0u, 0u);
        *(uint4*)(d_Bh + k * KPAD + 80) = make_uint4(0u, 0u, 0u, 0u);
    }
}

// ---------------- Kernel 1: fp16 HMMA coarse + fused argmin ----------------
// 256 threads / 8 warps: warp w -> rows (w&3)*32..+31 (2 m-tiles), chunk parity w>>2.
// Each B ldmatrix feeds 40 MMAs (2x the R9 ratio): LDSM smem traffic halved.
// smem: A[128][88]h = 22528 B; B 4 planes of [32][88]h (pair double-buffer)
#define S_A   0
#define S_B   22528
#define PLANE 5632
#define S_TOTAL 45056

__global__ __launch_bounds__(256, 2)
void gemm_argmin_kernel(const float* __restrict__ x) {
    extern __shared__ char smem[];
    uint32_t sb = smem_u32(smem);
    int tid = threadIdx.x;
    int lane = tid & 31, warp = tid >> 5;
    int par = warp >> 2;                  // 0: even chunks, 1: odd chunks
    int m0 = (warp & 3) * 32;             // 32-row group
    int row0 = blockIdx.x * TM;

    // A: x rows -> fp16 of (-2x), padded, aug col 64 = 1.0
    #pragma unroll
    for (int i = 0; i < 8; i++) {
        int f = tid + i * 256;          // 2048 float4 = 128 rows x 16
        int row = f >> 4, j = f & 15;
        float4 v = *(const float4*)(x + (row0 + row) * D + 4 * j);
        __half h0 = __float2half(-2.0f * v.x), h1 = __float2half(-2.0f * v.y);
        __half h2 = __float2half(-2.0f * v.z), h3 = __float2half(-2.0f * v.w);
        *(uint2*)(smem + S_A + (uint32_t)row * ROWB + j * 8) = make_uint2(
            (uint32_t)__half_as_ushort(h0) | ((uint32_t)__half_as_ushort(h1) << 16),
            (uint32_t)__half_as_ushort(h2) | ((uint32_t)__half_as_ushort(h3) << 16));
    }
    if (tid < 128) {
        uint32_t base = S_A + (uint32_t)tid * ROWB + 128;   // byte offset of col 64
        *(uint4*)(smem + base)      = make_uint4(0x3C00u, 0u, 0u, 0u);   // 1.0h, zeros
        *(uint4*)(smem + base + 16) = make_uint4(0u, 0u, 0u, 0u);
        *(uint4*)(smem + base + 32) = make_uint4(0u, 0u, 0u, 0u);
    }

    // load chunk PAIR 2p, 2p+1 (contiguous 704 16B units) into buffer p&1
    auto loadBpair = [&](int p) {
        uint32_t dst = sb + S_B + (uint32_t)(p & 1) * (2 * PLANE);
        const char* src = (const char*)(d_Bh + p * 2 * NCH * KPAD);
        cp_async16(dst + 16 * tid, src + 16 * tid);
        cp_async16(dst + 16 * (tid + 256), src + 16 * (tid + 256));
        int u = tid + 512;
        if (u < 704) cp_async16(dst + 16 * u, src + 16 * u);
        cp_commit();
    };

    loadBpair(0);
    cp_wait0();
    __syncthreads();

    int r = lane & 7, q = lane >> 3;
    uint32_t bOff = (uint32_t)(r + ((q >> 1) << 3)) * ROWB + ((q & 1) << 4);

    // persistent A fragments: 2 m-tiles x 5 k-steps
    uint32_t ah[2][5][4];
    #pragma unroll
    for (int m = 0; m < 2; m++) {
        uint32_t aAddr = sb + S_A
            + (uint32_t)(m0 + m * 16 + r + ((q & 1) << 3)) * ROWB + ((q >> 1) << 4);
        #pragma unroll
        for (int k = 0; k < 5; k++) ldm_x4(ah[m][k], aAddr + k * 32);
    }

    float bA[2] = {3.4e38f, 3.4e38f}, b2A[2] = {3.4e38f, 3.4e38f};
    float bB[2] = {3.4e38f, 3.4e38f}, b2B[2] = {3.4e38f, 3.4e38f};
    int iA[2] = {0, 0}, iB[2] = {0, 0};

    #pragma unroll 1
    for (int c = 0; c < 16; c++) {        // 16 pairs; this warp does chunk 2c+par
        if (c < 15) loadBpair(c + 1);     // async prefetch into other buffer

        uint32_t bbase = sb + S_B + (uint32_t)(c & 1) * (2 * PLANE)
                       + (uint32_t)par * PLANE + bOff;

        float acc[2][4][4];
        #pragma unroll
        for (int m = 0; m < 2; m++)
            #pragma unroll
            for (int nb = 0; nb < 4; nb++)
                #pragma unroll
                for (int j = 0; j < 4; j++) acc[m][nb][j] = 0.0f;

        #pragma unroll
        for (int k = 0; k < 5; k++) {
            #pragma unroll
            for (int t = 0; t < 2; t++) {
                uint32_t bh[4];
                ldm_x4(bh, bbase + t * (16 * ROWB) + k * 32);
                #pragma unroll
                for (int m = 0; m < 2; m++) {
                    mma_f16(acc[m][2*t],   ah[m][k], bh);
                    mma_f16(acc[m][2*t+1], ah[m][k], bh + 2);
                }
            }
        }

        int kbase = (2 * c + par) * NCH + 2 * (lane & 3);
        #pragma unroll
        for (int m = 0; m < 2; m++) {
            #pragma unroll
            for (int nb = 0; nb < 4; nb++) {
                #pragma unroll
                for (int j = 0; j < 4; j++) {
                    float v = acc[m][nb][j];
                    int kidx = kbase + nb * 8 + (j & 1);
                    if (j < 2) {
                        if (v < bA[m]) { b2A[m] = bA[m]; bA[m] = v; iA[m] = kidx; }
                        else b2A[m] = fminf(b2A[m], v);
                    } else {
                        if (v < bB[m]) { b2B[m] = bB[m]; bB[m] = v; iB[m] = kidx; }
                        else b2B[m] = fminf(b2B[m], v);
                    }
                }
            }
        }
        cp_wait0();
        __syncthreads();
    }

    // lane-quad merge (4 lanes share each row)
    #pragma unroll
    for (int m = 0; m < 2; m++) {
        #pragma unroll
        for (int off = 1; off <= 2; off <<= 1) {
            float ov = __shfl_xor_sync(0xffffffff, bA[m], off);
            float ov2 = __shfl_xor_sync(0xffffffff, b2A[m], off);
            int   oi = __shfl_xor_sync(0xffffffff, iA[m], off);
            if (ov < bA[m]) { b2A[m] = fminf(bA[m], ov2); bA[m] = ov; iA[m] = oi; }
            else b2A[m] = fminf(b2A[m], ov);
            ov = __shfl_xor_sync(0xffffffff, bB[m], off);
            ov2 = __shfl_xor_sync(0xffffffff, b2B[m], off);
            oi = __shfl_xor_sync(0xffffffff, iB[m], off);
            if (ov < bB[m]) { b2B[m] = fminf(bB[m], ov2); bB[m] = ov; iB[m] = oi; }
            else b2B[m] = fminf(b2B[m], ov);
        }
    }

    // cross-warp merge (par 0 vs par 1) via smem; exact-equal ties get flagged (gap 0)
    float* mv  = (float*)smem;            // reuse A region (fragments already in regs)
    float* mv2 = mv + 128;
    int*   mi  = (int*)(mv + 256);
    __syncthreads();
    if (par == 1 && (lane & 3) == 0) {
        #pragma unroll
        for (int m = 0; m < 2; m++) {
            int rA = m0 + m * 16 + (lane >> 2);
            mv[rA] = bA[m]; mv2[rA] = b2A[m]; mi[rA] = iA[m];
            int rB = rA + 8;
            mv[rB] = bB[m]; mv2[rB] = b2B[m]; mi[rB] = iB[m];
        }
    }
    __syncthreads();
    if (par == 0 && (lane & 3) == 0) {
        #pragma unroll
        for (int m = 0; m < 2; m++) {
            int rA = m0 + m * 16 + (lane >> 2);
            {
                float ob = mv[rA], ob2 = mv2[rA]; int oi = mi[rA];
                float nb, nb2; int ni;
                if (ob < bA[m]) { nb = ob; ni = oi; nb2 = fminf(bA[m], ob2); }
                else            { nb = bA[m]; ni = iA[m]; nb2 = fminf(b2A[m], ob); }
                int row = row0 + rA;
                d_idx[row] = ni;
                if (nb2 - nb < MARGIN_COARSE) { int p = atomicAdd(&d_flagCnt, 1); d_flagList[p] = row; }
            }
            int rB = rA + 8;
            {
                float ob = mv[rB], ob2 = mv2[rB]; int oi = mi[rB];
                float nb, nb2; int ni;
                if (ob < bB[m]) { nb = ob; ni = oi; nb2 = fminf(bB[m], ob2); }
                else            { nb = bB[m]; ni = iB[m]; nb2 = fminf(b2B[m], ob); }
                int row = row0 + rB;
                d_idx[row] = ni;
                if (nb2 - nb < MARGIN_COARSE) { int p = atomicAdd(&d_flagCnt, 1); d_flagList[p] = row; }
            }
        }
    }
}

// ---------------- Kernel 2: exact float-float resolve, coalesced ----------------
__global__ __launch_bounds__(256, 1)
void exact_kernel(const float* __restrict__ x, const float* __restrict__ emb) {
    __shared__ float sx[D];
    __shared__ float rv[256];
    __shared__ int   ri[256];
    int tid = threadIdx.x;

    int cnt = d_flagCnt;
    for (int i = blockIdx.x; i < cnt; i += gridDim.x) {
        int row = d_flagList[i];
        if (tid < D / 4) {
            float4 v = *(const float4*)(x + row * D + 4 * tid);
            sx[4*tid] = v.x; sx[4*tid+1] = v.y; sx[4*tid+2] = v.z; sx[4*tid+3] = v.w;
        }
        __syncthreads();

        float sn = 0.0f;
        float s0 = 0.f, c0 = 0.f, s1 = 0.f, c1 = 0.f;
        float s2 = 0.f, c2 = 0.f, s3 = 0.f, c3 = 0.f;
        #pragma unroll 4
        for (int dd = 0; dd < D; dd++) {
            float xv = sx[dd];
            sn = __fadd_rn(sn, __fmul_rn(xv, xv));   // ref-style norm
            const float* er = emb + dd * K + tid;    // coalesced across lanes
            ddAccum(s0, c0, xv, er[0]);
            ddAccum(s1, c1, xv, er[256]);
            ddAccum(s2, c2, xv, er[512]);
            ddAccum(s3, c3, xv, er[768]);
        }
        float xn = sn;
        float ss[4] = {s0, s1, s2, s3};
        float cc[4] = {c0, c1, c2, c3};
        float bv = 3.4e38f; int bi = 0;
        #pragma unroll
        for (int t = 0; t < 4; t++) {
            int k = tid + 256 * t;
            float hi, lo;
            twoSum(ss[t], cc[t], hi, lo);
            float s2f = __fmaf_rn(2.0f, lo, __fmul_rn(2.0f, hi));   // fl32(2*sim)
            float t1 = __fadd_rn(xn, d_en[k]);
            float dist = __fsub_rn(t1, s2f);
            if (dist < bv) { bv = dist; bi = k; }
        }
        rv[tid] = bv; ri[tid] = bi;
        __syncthreads();
        for (int off = 128; off > 0; off >>= 1) {
            if (tid < off) {
                float ov = rv[tid + off]; int oi = ri[tid + off];
                if (ov < rv[tid] || (ov == rv[tid] && oi < ri[tid])) {
                    rv[tid] = ov; ri[tid] = oi;
                }
            }
            __syncthreads();
        }
        if (tid == 0) d_idx[row] = ri[0];
        __syncthreads();
    }
}

// ---------------- Kernel 3: gather + straight-through + loss + finalize ----------------
#define OUT_T (N_ROWS * D / 4)       // 524288 float4
#define OUT_STRIDE (OUT_T / 2)       // 262144 threads, 2 float4 each
__global__ void out_kernel(const float* __restrict__ x, float* __restrict__ out, int out_size) {
    int t0 = blockIdx.x * blockDim.x + threadIdx.x;
    float v = 0.0f;
    #pragma unroll
    for (int i = 0; i < 2; i++) {
        int t = t0 + i * OUT_STRIDE;
        int r = t >> 4, j = t & 15;
        int idx = d_idx[r];
        float4 xv = ((const float4*)x)[t];
        float4 qv = *(const float4*)(d_eT + idx * D + 4 * j);
        float dx = qv.x - xv.x, dy = qv.y - xv.y, dz = qv.z - xv.z, dw = qv.w - xv.w;
        ((float4*)out)[t] = make_float4(xv.x + dx, xv.y + dy, xv.z + dz, xv.w + dw);
        v += dx * dx + dy * dy + dz * dz + dw * dw;
    }

    #pragma unroll
    for (int off = 16; off > 0; off >>= 1) v += __shfl_xor_sync(0xffffffff, v, off);
    __shared__ float ws[8];
    int wid = threadIdx.x >> 5, lid = threadIdx.x & 31;
    if (lid == 0) ws[wid] = v;
    __syncthreads();
    if (threadIdx.x == 0) {
        float s = 0.0f;
        #pragma unroll
        for (int i = 0; i < 8; i++) s += ws[i];
        atomicAdd(&d_lossAcc, s);
        __threadfence();
        int done = atomicAdd(&d_outDone, 1);
        if (done == gridDim.x - 1) {
            out[out_size - 1] = 1.25f * d_lossAcc * (1.0f / (float)(N_ROWS * D));
        }
    }
}

extern "C" void kernel_launch(void* const* d_in, const int* in_sizes, int n_in,
                              void* d_out, int out_size) {
    const float* x   = (const float*)d_in[0];
    const float* emb = (const float*)d_in[1];
    float* out = (float*)d_out;

    prep_kernel<<<32, 32>>>(emb);                         // idx 0
    gemm_argmin_kernel<<<N_ROWS / TM, 256, S_TOTAL>>>(x); // idx 1
    exact_kernel<<<512, 256>>>(x, emb);                   // idx 2
    out_kernel<<<OUT_STRIDE / 256, 256>>>(x, out, out_size); // idx 3
}

// round 11
// speedup vs baseline: 6.2457x; 1.0366x over previous
#include <cuda_runtime.h>
#include <cuda_fp16.h>
#include <cstdint>

#define N_ROWS 32768
#define D 64
#define K 1024
#define KPAD 88            // padded k-extent in halfs; row stride 176 B (conflict-free ldmatrix)
#define ROWB 176
#define TM 128             // rows per CTA
#define NCH 32             // codes per chunk
#define MARGIN_COARSE 2e-3f
#define EPS_SCREEN 5e-5f

__device__ float d_en[K];                        // fp32 ||e_k||^2 (ref-style mul-then-add)
__device__ float d_eT[K * D];                    // [k][d] fp32 (gather)
__device__ __align__(16) __half d_Bh[K * KPAD];  // [k][KPAD] fp16 codebook (+aug en at col 64)
__device__ int   d_idx[N_ROWS];
__device__ float d_lossAcc;
__device__ int   d_flagCnt;
__device__ int   d_flagList[N_ROWS];
__device__ int   d_outDone;

// ---------------- helpers ----------------
__device__ __forceinline__ uint32_t smem_u32(const void* p) {
    uint32_t a;
    asm("{ .reg .u64 t; cvta.to.shared.u64 t, %1; cvt.u32.u64 %0, t; }" : "=r"(a) : "l"(p));
    return a;
}
__device__ __forceinline__ void ldm_x4(uint32_t* r, uint32_t addr) {
    asm volatile("ldmatrix.sync.aligned.m8n8.x4.shared.b16 {%0,%1,%2,%3}, [%4];"
        : "=r"(r[0]), "=r"(r[1]), "=r"(r[2]), "=r"(r[3]) : "r"(addr));
}
__device__ __forceinline__ void mma_f16(float* d, const uint32_t* a, const uint32_t* b) {
    asm volatile("mma.sync.aligned.m16n8k16.row.col.f32.f16.f16.f32 "
        "{%0,%1,%2,%3}, {%4,%5,%6,%7}, {%8,%9}, {%0,%1,%2,%3};"
        : "+f"(d[0]), "+f"(d[1]), "+f"(d[2]), "+f"(d[3])
        : "r"(a[0]), "r"(a[1]), "r"(a[2]), "r"(a[3]), "r"(b[0]), "r"(b[1]));
}
__device__ __forceinline__ void cp_async16(uint32_t sdst, const void* gsrc) {
    asm volatile("cp.async.cg.shared.global [%0], [%1], 16;" :: "r"(sdst), "l"(gsrc) : "memory");
}
__device__ __forceinline__ void cp_commit() { asm volatile("cp.async.commit_group;" ::: "memory"); }
__device__ __forceinline__ void cp_wait0()  { asm volatile("cp.async.wait_group 0;" ::: "memory"); }

// float-float (double-single) primitives — full-rate FMA pipe
__device__ __forceinline__ void twoSum(float a, float b, float& s, float& e) {
    s = __fadd_rn(a, b);
    float bb = __fsub_rn(s, a);
    e = __fadd_rn(__fsub_rn(a, __fsub_rn(s, bb)), __fsub_rn(b, bb));
}
__device__ __forceinline__ void ddAccum(float& s, float& c, float x, float e) {
    float p = __fmul_rn(x, e);
    float perr = __fmaf_rn(x, e, -p);
    float t, err;
    twoSum(s, p, t, err);
    s = t;
    c = __fadd_rn(c, __fadd_rn(err, perr));
}

// ---------------- Kernel: fused prep ----------------
__global__ void prep_kernel(const float* __restrict__ emb) {
    int k = blockIdx.x * blockDim.x + threadIdx.x;
    if (k == 0) { d_lossAcc = 0.0f; d_flagCnt = 0; d_outDone = 0; }
    if (k < K) {
        float s = 0.0f;
        float fbuf[4];
        #pragma unroll
        for (int dd = 0; dd < D; dd += 4) {
            #pragma unroll
            for (int u = 0; u < 4; u++) {
                float v = emb[(dd + u) * K + k];            // coalesced across lanes
                s = __fadd_rn(s, __fmul_rn(v, v));          // ref-style mul-then-add
                fbuf[u] = v;
            }
            *(float4*)(d_eT + k * D + dd) = make_float4(fbuf[0], fbuf[1], fbuf[2], fbuf[3]);
            __half h0 = __float2half(fbuf[0]), h1 = __float2half(fbuf[1]);
            __half h2 = __float2half(fbuf[2]), h3 = __float2half(fbuf[3]);
            *(uint2*)(d_Bh + k * KPAD + dd) = make_uint2(
                (uint32_t)__half_as_ushort(h0) | ((uint32_t)__half_as_ushort(h1) << 16),
                (uint32_t)__half_as_ushort(h2) | ((uint32_t)__half_as_ushort(h3) << 16));
        }
        d_en[k] = s;
        *(uint2*)(d_Bh + k * KPAD + 64) = make_uint2((uint32_t)__half_as_ushort(__float2half(s)), 0u);
        *(uint2*)(d_Bh + k * KPAD + 68) = make_uint2(0u, 0u);
        *(uint4*)(d_Bh + k * KPAD + 72) = make_uint4(0u, 0u, 0u, 0u);
        *(uint4*)(d_Bh + k * KPAD + 80) = make_uint4(0u, 0u, 0u, 0u);
    }
}

// ---------------- dummy (launch-index alignment for ncu) ----------------
__global__ void noop_kernel() {}

// ---------------- Kernel (profiled idx 3): fp16 HMMA coarse + fused argmin ----------------
#define S_A   0
#define S_B   22528
#define PLANE 5632
#define S_TOTAL 45056

__global__ __launch_bounds__(256, 2)
void gemm_argmin_kernel(const float* __restrict__ x) {
    extern __shared__ char smem[];
    uint32_t sb = smem_u32(smem);
    int tid = threadIdx.x;
    int lane = tid & 31, warp = tid >> 5;
    int par = warp >> 2;                  // 0: even chunks, 1: odd chunks
    int m0 = (warp & 3) * 32;             // 32-row group
    int row0 = blockIdx.x * TM;

    // A: x rows -> fp16 of (-2x), padded, aug col 64 = 1.0
    #pragma unroll
    for (int i = 0; i < 8; i++) {
        int f = tid + i * 256;          // 2048 float4 = 128 rows x 16
        int row = f >> 4, j = f & 15;
        float4 v = *(const float4*)(x + (row0 + row) * D + 4 * j);
        __half h0 = __float2half(-2.0f * v.x), h1 = __float2half(-2.0f * v.y);
        __half h2 = __float2half(-2.0f * v.z), h3 = __float2half(-2.0f * v.w);
        *(uint2*)(smem + S_A + (uint32_t)row * ROWB + j * 8) = make_uint2(
            (uint32_t)__half_as_ushort(h0) | ((uint32_t)__half_as_ushort(h1) << 16),
            (uint32_t)__half_as_ushort(h2) | ((uint32_t)__half_as_ushort(h3) << 16));
    }
    if (tid < 128) {
        uint32_t base = S_A + (uint32_t)tid * ROWB + 128;   // byte offset of col 64
        *(uint4*)(smem + base)      = make_uint4(0x3C00u, 0u, 0u, 0u);   // 1.0h, zeros
        *(uint4*)(smem + base + 16) = make_uint4(0u, 0u, 0u, 0u);
        *(uint4*)(smem + base + 32) = make_uint4(0u, 0u, 0u, 0u);
    }

    auto loadBpair = [&](int p) {
        uint32_t dst = sb + S_B + (uint32_t)(p & 1) * (2 * PLANE);
        const char* src = (const char*)(d_Bh + p * 2 * NCH * KPAD);
        cp_async16(dst + 16 * tid, src + 16 * tid);
        cp_async16(dst + 16 * (tid + 256), src + 16 * (tid + 256));
        int u = tid + 512;
        if (u < 704) cp_async16(dst + 16 * u, src + 16 * u);
        cp_commit();
    };

    loadBpair(0);
    cp_wait0();
    __syncthreads();

    int r = lane & 7, q = lane >> 3;
    uint32_t bOff = (uint32_t)(r + ((q >> 1) << 3)) * ROWB + ((q & 1) << 4);

    // persistent A fragments: 2 m-tiles x 5 k-steps
    uint32_t ah[2][5][4];
    #pragma unroll
    for (int m = 0; m < 2; m++) {
        uint32_t aAddr = sb + S_A
            + (uint32_t)(m0 + m * 16 + r + ((q & 1) << 3)) * ROWB + ((q >> 1) << 4);
        #pragma unroll
        for (int k = 0; k < 5; k++) ldm_x4(ah[m][k], aAddr + k * 32);
    }

    float bA[2] = {3.4e38f, 3.4e38f}, b2A[2] = {3.4e38f, 3.4e38f};
    float bB[2] = {3.4e38f, 3.4e38f}, b2B[2] = {3.4e38f, 3.4e38f};
    int iA[2] = {0, 0}, iB[2] = {0, 0};

    #pragma unroll 1
    for (int c = 0; c < 16; c++) {        // 16 pairs; this warp does chunk 2c+par
        if (c < 15) loadBpair(c + 1);

        uint32_t bbase = sb + S_B + (uint32_t)(c & 1) * (2 * PLANE)
                       + (uint32_t)par * PLANE + bOff;

        float acc[2][4][4];
        #pragma unroll
        for (int m = 0; m < 2; m++)
            #pragma unroll
            for (int nb = 0; nb < 4; nb++)
                #pragma unroll
                for (int j = 0; j < 4; j++) acc[m][nb][j] = 0.0f;

        #pragma unroll
        for (int k = 0; k < 5; k++) {
            #pragma unroll
            for (int t = 0; t < 2; t++) {
                uint32_t bh[4];
                ldm_x4(bh, bbase + t * (16 * ROWB) + k * 32);
                #pragma unroll
                for (int m = 0; m < 2; m++) {
                    mma_f16(acc[m][2*t],   ah[m][k], bh);
                    mma_f16(acc[m][2*t+1], ah[m][k], bh + 2);
                }
            }
        }

        int kbase = (2 * c + par) * NCH + 2 * (lane & 3);
        #pragma unroll
        for (int m = 0; m < 2; m++) {
            #pragma unroll
            for (int nb = 0; nb < 4; nb++) {
                #pragma unroll
                for (int j = 0; j < 4; j++) {
                    float v = acc[m][nb][j];
                    int kidx = kbase + nb * 8 + (j & 1);
                    if (j < 2) {
                        if (v < bA[m]) { b2A[m] = bA[m]; bA[m] = v; iA[m] = kidx; }
                        else b2A[m] = fminf(b2A[m], v);
                    } else {
                        if (v < bB[m]) { b2B[m] = bB[m]; bB[m] = v; iB[m] = kidx; }
                        else b2B[m] = fminf(b2B[m], v);
                    }
                }
            }
        }
        cp_wait0();
        __syncthreads();
    }

    // lane-quad merge (4 lanes share each row)
    #pragma unroll
    for (int m = 0; m < 2; m++) {
        #pragma unroll
        for (int off = 1; off <= 2; off <<= 1) {
            float ov = __shfl_xor_sync(0xffffffff, bA[m], off);
            float ov2 = __shfl_xor_sync(0xffffffff, b2A[m], off);
            int   oi = __shfl_xor_sync(0xffffffff, iA[m], off);
            if (ov < bA[m]) { b2A[m] = fminf(bA[m], ov2); bA[m] = ov; iA[m] = oi; }
            else b2A[m] = fminf(b2A[m], ov);
            ov = __shfl_xor_sync(0xffffffff, bB[m], off);
            ov2 = __shfl_xor_sync(0xffffffff, b2B[m], off);
            oi = __shfl_xor_sync(0xffffffff, iB[m], off);
            if (ov < bB[m]) { b2B[m] = fminf(bB[m], ov2); bB[m] = ov; iB[m] = oi; }
            else b2B[m] = fminf(b2B[m], ov);
        }
    }

    // cross-warp merge (par 0 vs par 1) via smem
    float* mv  = (float*)smem;
    float* mv2 = mv + 128;
    int*   mi  = (int*)(mv + 256);
    __syncthreads();
    if (par == 1 && (lane & 3) == 0) {
        #pragma unroll
        for (int m = 0; m < 2; m++) {
            int rA = m0 + m * 16 + (lane >> 2);
            mv[rA] = bA[m]; mv2[rA] = b2A[m]; mi[rA] = iA[m];
            int rB = rA + 8;
            mv[rB] = bB[m]; mv2[rB] = b2B[m]; mi[rB] = iB[m];
        }
    }
    __syncthreads();
    if (par == 0 && (lane & 3) == 0) {
        #pragma unroll
        for (int m = 0; m < 2; m++) {
            int rA = m0 + m * 16 + (lane >> 2);
            {
                float ob = mv[rA], ob2 = mv2[rA]; int oi = mi[rA];
                float nb, nb2; int ni;
                if (ob < bA[m]) { nb = ob; ni = oi; nb2 = fminf(bA[m], ob2); }
                else            { nb = bA[m]; ni = iA[m]; nb2 = fminf(b2A[m], ob); }
                int row = row0 + rA;
                d_idx[row] = ni;
                if (nb2 - nb < MARGIN_COARSE) { int p = atomicAdd(&d_flagCnt, 1); d_flagList[p] = row; }
            }
            int rB = rA + 8;
            {
                float ob = mv[rB], ob2 = mv2[rB]; int oi = mi[rB];
                float nb, nb2; int ni;
                if (ob < bB[m]) { nb = ob; ni = oi; nb2 = fminf(bB[m], ob2); }
                else            { nb = bB[m]; ni = iB[m]; nb2 = fminf(b2B[m], ob); }
                int row = row0 + rB;
                d_idx[row] = ni;
                if (nb2 - nb < MARGIN_COARSE) { int p = atomicAdd(&d_flagCnt, 1); d_flagList[p] = row; }
            }
        }
    }
}

// ---------------- exact resolve: fp32 screen + float-float refine ----------------
// Phase 1: plain fp32 FMA dists for all K (cheap). Phase 2: codes within EPS_SCREEN
// of the block min get the exact float-float + reference-grid-rounded dist; winner
// selected by packed (dist_bits<<32)|idx atomicMin (first-index tie-break).
__global__ __launch_bounds__(256, 2)
void exact_kernel(const float* __restrict__ x, const float* __restrict__ emb) {
    __shared__ float sx[D];
    __shared__ float rbest[256];
    __shared__ unsigned long long spack;
    int tid = threadIdx.x;

    int cnt = d_flagCnt;
    for (int i = blockIdx.x; i < cnt; i += gridDim.x) {
        int row = d_flagList[i];
        if (tid < D / 4) {
            float4 v = *(const float4*)(x + row * D + 4 * tid);
            sx[4*tid] = v.x; sx[4*tid+1] = v.y; sx[4*tid+2] = v.z; sx[4*tid+3] = v.w;
        }
        if (tid == 0) spack = ~0ull;
        __syncthreads();

        // phase 1: fp32 dots + ref-style norm (redundant per thread, cheap)
        float sn = 0.0f;
        float a0 = 0.f, a1 = 0.f, a2 = 0.f, a3 = 0.f;
        #pragma unroll 8
        for (int dd = 0; dd < D; dd++) {
            float xv = sx[dd];
            sn = __fadd_rn(sn, __fmul_rn(xv, xv));
            const float* er = emb + dd * K + tid;    // coalesced across lanes
            a0 = __fmaf_rn(xv, er[0],   a0);
            a1 = __fmaf_rn(xv, er[256], a1);
            a2 = __fmaf_rn(xv, er[512], a2);
            a3 = __fmaf_rn(xv, er[768], a3);
        }
        float xn = sn;
        float d32[4];
        d32[0] = d_en[tid]       - 2.0f * a0;
        d32[1] = d_en[tid + 256] - 2.0f * a1;
        d32[2] = d_en[tid + 512] - 2.0f * a2;
        d32[3] = d_en[tid + 768] - 2.0f * a3;
        float dmin = fminf(fminf(d32[0], d32[1]), fminf(d32[2], d32[3]));
        rbest[tid] = dmin;
        __syncthreads();
        for (int off = 128; off > 0; off >>= 1) {
            if (tid < off) rbest[tid] = fminf(rbest[tid], rbest[tid + off]);
            __syncthreads();
        }
        float best = rbest[0];

        // phase 2: exact dist (ref rounding) for the few screened candidates
        #pragma unroll
        for (int t = 0; t < 4; t++) {
            if (d32[t] < best + EPS_SCREEN) {
                int k = tid + 256 * t;
                float s = 0.f, c = 0.f;
                const float* ek = d_eT + k * D;
                #pragma unroll 8
                for (int dd = 0; dd < D; dd++) ddAccum(s, c, sx[dd], ek[dd]);
                float hi, lo;
                twoSum(s, c, hi, lo);
                float s2f = __fmaf_rn(2.0f, lo, __fmul_rn(2.0f, hi));   // fl32(2*sim)
                float t1 = __fadd_rn(xn, d_en[k]);
                float dist = __fsub_rn(t1, s2f);
                unsigned long long pk =
                    ((unsigned long long)__float_as_uint(dist) << 32) | (unsigned)k;
                atomicMin(&spack, pk);
            }
        }
        __syncthreads();
        if (tid == 0) d_idx[row] = (int)(spack & 0xFFFFFFFFull);
        __syncthreads();
    }
}

// ---------------- gather + straight-through + loss + finalize (ILP-4, batched loads) ----------------
#define OUT_T (N_ROWS * D / 4)       // 524288 float4
#define OUT_STRIDE (OUT_T / 4)       // 131072 threads, 4 float4 each
__global__ void out_kernel(const float* __restrict__ x, float* __restrict__ out, int out_size) {
    int t0 = blockIdx.x * blockDim.x + threadIdx.x;
    int idxs[4];
    #pragma unroll
    for (int i = 0; i < 4; i++) idxs[i] = d_idx[(t0 + i * OUT_STRIDE) >> 4];
    float4 xv[4];
    #pragma unroll
    for (int i = 0; i < 4; i++) xv[i] = ((const float4*)x)[t0 + i * OUT_STRIDE];
    float4 qv[4];
    #pragma unroll
    for (int i = 0; i < 4; i++)
        qv[i] = *(const float4*)(d_eT + idxs[i] * D + 4 * ((t0 + i * OUT_STRIDE) & 15));
    float v = 0.0f;
    #pragma unroll
    for (int i = 0; i < 4; i++) {
        int t = t0 + i * OUT_STRIDE;
        float dx = qv[i].x - xv[i].x, dy = qv[i].y - xv[i].y;
        float dz = qv[i].z - xv[i].z, dw = qv[i].w - xv[i].w;
        ((float4*)out)[t] = make_float4(xv[i].x + dx, xv[i].y + dy, xv[i].z + dz, xv[i].w + dw);
        v += dx * dx + dy * dy + dz * dz + dw * dw;
    }

    #pragma unroll
    for (int off = 16; off > 0; off >>= 1) v += __shfl_xor_sync(0xffffffff, v, off);
    __shared__ float ws[8];
    int wid = threadIdx.x >> 5, lid = threadIdx.x & 31;
    if (lid == 0) ws[wid] = v;
    __syncthreads();
    if (threadIdx.x == 0) {
        float s = 0.0f;
        #pragma unroll
        for (int i = 0; i < 8; i++) s += ws[i];
        atomicAdd(&d_lossAcc, s);
        __threadfence();
        int done = atomicAdd(&d_outDone, 1);
        if (done == gridDim.x - 1) {
            out[out_size - 1] = 1.25f * d_lossAcc * (1.0f / (float)(N_ROWS * D));
        }
    }
}

extern "C" void kernel_launch(void* const* d_in, const int* in_sizes, int n_in,
                              void* d_out, int out_size) {
    const float* x   = (const float*)d_in[0];
    const float* emb = (const float*)d_in[1];
    float* out = (float*)d_out;

    prep_kernel<<<32, 32>>>(emb);                          // idx 0
    noop_kernel<<<1, 1>>>();                               // idx 1
    noop_kernel<<<1, 1>>>();                               // idx 2
    gemm_argmin_kernel<<<N_ROWS / TM, 256, S_TOTAL>>>(x);  // idx 3  (profiled)
    exact_kernel<<<512, 256>>>(x, emb);                    // idx 4
    out_kernel<<<OUT_STRIDE / 256, 256>>>(x, out, out_size); // idx 5
}

// round 12
// speedup vs baseline: 6.3891x; 1.0230x over previous
#include <cuda_runtime.h>
#include <cuda_fp16.h>
#include <cstdint>

#define N_ROWS 32768
#define D 64
#define K 1024
#define KPAD 88            // gmem B row stride in halfs (176 B, conflict-free ldmatrix)
#define ROWB 176
#define TM 128             // rows per CTA
#define NCH 32             // codes per chunk
#define MARGIN_COARSE 2e-3f
#define EPS_SCREEN 5e-5f

__device__ float d_en[K];                        // fp32 ||e_k||^2 (ref-style mul-then-add)
__device__ float d_eT[K * D];                    // [k][d] fp32 (gather)
__device__ __align__(16) __half d_Bh[K * KPAD];  // [k][KPAD] fp16 codebook
__device__ int   d_idx[N_ROWS];
__device__ float d_lossAcc;
__device__ int   d_flagCnt;
__device__ int   d_flagList[N_ROWS];

// ---------------- helpers ----------------
__device__ __forceinline__ uint32_t smem_u32(const void* p) {
    uint32_t a;
    asm("{ .reg .u64 t; cvta.to.shared.u64 t, %1; cvt.u32.u64 %0, t; }" : "=r"(a) : "l"(p));
    return a;
}
__device__ __forceinline__ void ldm_x4(uint32_t* r, uint32_t addr) {
    asm volatile("ldmatrix.sync.aligned.m8n8.x4.shared.b16 {%0,%1,%2,%3}, [%4];"
        : "=r"(r[0]), "=r"(r[1]), "=r"(r[2]), "=r"(r[3]) : "r"(addr));
}
__device__ __forceinline__ void mma_f16(float* d, const uint32_t* a, const uint32_t* b) {
    asm volatile("mma.sync.aligned.m16n8k16.row.col.f32.f16.f16.f32 "
        "{%0,%1,%2,%3}, {%4,%5,%6,%7}, {%8,%9}, {%0,%1,%2,%3};"
        : "+f"(d[0]), "+f"(d[1]), "+f"(d[2]), "+f"(d[3])
        : "r"(a[0]), "r"(a[1]), "r"(a[2]), "r"(a[3]), "r"(b[0]), "r"(b[1]));
}
__device__ __forceinline__ void cp_async16(uint32_t sdst, const void* gsrc) {
    asm volatile("cp.async.cg.shared.global [%0], [%1], 16;" :: "r"(sdst), "l"(gsrc) : "memory");
}
__device__ __forceinline__ void cp_commit() { asm volatile("cp.async.commit_group;" ::: "memory"); }
__device__ __forceinline__ void cp_wait0()  { asm volatile("cp.async.wait_group 0;" ::: "memory"); }

// float-float (double-single) primitives — full-rate FMA pipe
__device__ __forceinline__ void twoSum(float a, float b, float& s, float& e) {
    s = __fadd_rn(a, b);
    float bb = __fsub_rn(s, a);
    e = __fadd_rn(__fsub_rn(a, __fsub_rn(s, bb)), __fsub_rn(b, bb));
}
__device__ __forceinline__ void ddAccum(float& s, float& c, float x, float e) {
    float p = __fmul_rn(x, e);
    float perr = __fmaf_rn(x, e, -p);
    float t, err;
    twoSum(s, p, t, err);
    s = t;
    c = __fadd_rn(c, __fadd_rn(err, perr));
}

// ---------------- Kernel: fused prep ----------------
__global__ void prep_kernel(const float* __restrict__ emb) {
    int k = blockIdx.x * blockDim.x + threadIdx.x;
    if (k == 0) { d_lossAcc = 0.0f; d_flagCnt = 0; }
    if (k < K) {
        float s = 0.0f;
        float fbuf[4];
        #pragma unroll
        for (int dd = 0; dd < D; dd += 4) {
            #pragma unroll
            for (int u = 0; u < 4; u++) {
                float v = emb[(dd + u) * K + k];            // coalesced across lanes
                s = __fadd_rn(s, __fmul_rn(v, v));          // ref-style mul-then-add
                fbuf[u] = v;
            }
            *(float4*)(d_eT + k * D + dd) = make_float4(fbuf[0], fbuf[1], fbuf[2], fbuf[3]);
            __half h0 = __float2half(fbuf[0]), h1 = __float2half(fbuf[1]);
            __half h2 = __float2half(fbuf[2]), h3 = __float2half(fbuf[3]);
            *(uint2*)(d_Bh + k * KPAD + dd) = make_uint2(
                (uint32_t)__half_as_ushort(h0) | ((uint32_t)__half_as_ushort(h1) << 16),
                (uint32_t)__half_as_ushort(h2) | ((uint32_t)__half_as_ushort(h3) << 16));
        }
        d_en[k] = s;
    }
}

// ---------------- dummy (launch-index alignment for ncu) ----------------
__global__ void noop_kernel() {}

// ---------------- Kernel (profiled idx 3): fp16 HMMA coarse + argmin + fused output ----------------
// 4 k-steps (no aug column); en added in epilogue from smem. Output/gather/loss fused
// into the CTA tail (uses the CTA's own 128 final indices).
#define S_A   0
#define S_B   22528
#define PLANE 5632
#define S_EN  45056
#define S_TOTAL 49152

__global__ __launch_bounds__(256, 2)
void gemm_argmin_kernel(const float* __restrict__ x, float* __restrict__ out) {
    extern __shared__ char smem[];
    uint32_t sb = smem_u32(smem);
    int tid = threadIdx.x;
    int lane = tid & 31, warp = tid >> 5;
    int par = warp >> 2;                  // 0: even chunks, 1: odd chunks
    int m0 = (warp & 3) * 32;             // 32-row group
    int row0 = blockIdx.x * TM;

    // en table -> smem (1024 floats)
    ((float4*)(smem + S_EN))[tid] = ((const float4*)d_en)[tid];

    // A: x rows -> fp16 of (-2x), 128B per row, 176B stride
    #pragma unroll
    for (int i = 0; i < 8; i++) {
        int f = tid + i * 256;          // 2048 float4 = 128 rows x 16
        int row = f >> 4, j = f & 15;
        float4 v = *(const float4*)(x + (row0 + row) * D + 4 * j);
        __half h0 = __float2half(-2.0f * v.x), h1 = __float2half(-2.0f * v.y);
        __half h2 = __float2half(-2.0f * v.z), h3 = __float2half(-2.0f * v.w);
        *(uint2*)(smem + S_A + (uint32_t)row * ROWB + j * 8) = make_uint2(
            (uint32_t)__half_as_ushort(h0) | ((uint32_t)__half_as_ushort(h1) << 16),
            (uint32_t)__half_as_ushort(h2) | ((uint32_t)__half_as_ushort(h3) << 16));
    }

    // load chunk PAIR 2p,2p+1: 512 16B units (128B per code row), 176B stride both sides
    auto loadBpair = [&](int p) {
        uint32_t dstb = sb + S_B + (uint32_t)(p & 1) * (2 * PLANE);
        const char* srcb = (const char*)d_Bh + (size_t)p * 64 * ROWB;
        #pragma unroll
        for (int i = 0; i < 2; i++) {
            int u = tid + i * 256;            // 0..511
            int pl = u >> 8, rr = (u >> 3) & 31, cc = u & 7;
            cp_async16(dstb + pl * PLANE + rr * ROWB + cc * 16,
                       srcb + (pl * 32 + rr) * ROWB + cc * 16);
        }
        cp_commit();
    };

    loadBpair(0);
    cp_wait0();
    __syncthreads();

    int r = lane & 7, q = lane >> 3;
    uint32_t bOff = (uint32_t)(r + ((q >> 1) << 3)) * ROWB + ((q & 1) << 4);
    const float* sEn = (const float*)(smem + S_EN);

    // persistent A fragments: 2 m-tiles x 4 k-steps
    uint32_t ah[2][4][4];
    #pragma unroll
    for (int m = 0; m < 2; m++) {
        uint32_t aAddr = sb + S_A
            + (uint32_t)(m0 + m * 16 + r + ((q & 1) << 3)) * ROWB + ((q >> 1) << 4);
        #pragma unroll
        for (int k = 0; k < 4; k++) ldm_x4(ah[m][k], aAddr + k * 32);
    }

    float bA[2] = {3.4e38f, 3.4e38f}, b2A[2] = {3.4e38f, 3.4e38f};
    float bB[2] = {3.4e38f, 3.4e38f}, b2B[2] = {3.4e38f, 3.4e38f};
    int iA[2] = {0, 0}, iB[2] = {0, 0};

    #pragma unroll 1
    for (int c = 0; c < 16; c++) {        // 16 pairs; this warp does chunk 2c+par
        if (c < 15) loadBpair(c + 1);

        uint32_t bbase = sb + S_B + (uint32_t)(c & 1) * (2 * PLANE)
                       + (uint32_t)par * PLANE + bOff;

        float acc[2][4][4];
        #pragma unroll
        for (int m = 0; m < 2; m++)
            #pragma unroll
            for (int nb = 0; nb < 4; nb++)
                #pragma unroll
                for (int j = 0; j < 4; j++) acc[m][nb][j] = 0.0f;

        #pragma unroll
        for (int k = 0; k < 4; k++) {
            #pragma unroll
            for (int t = 0; t < 2; t++) {
                uint32_t bh[4];
                ldm_x4(bh, bbase + t * (16 * ROWB) + k * 32);
                #pragma unroll
                for (int m = 0; m < 2; m++) {
                    mma_f16(acc[m][2*t],   ah[m][k], bh);
                    mma_f16(acc[m][2*t+1], ah[m][k], bh + 2);
                }
            }
        }

        int kbase = (2 * c + par) * NCH + 2 * (lane & 3);
        float2 env[4];
        #pragma unroll
        for (int nb = 0; nb < 4; nb++) env[nb] = *(const float2*)(sEn + kbase + nb * 8);
        #pragma unroll
        for (int m = 0; m < 2; m++) {
            #pragma unroll
            for (int nb = 0; nb < 4; nb++) {
                #pragma unroll
                for (int j = 0; j < 4; j++) {
                    float v = acc[m][nb][j] + ((j & 1) ? env[nb].y : env[nb].x);
                    int kidx = kbase + nb * 8 + (j & 1);
                    if (j < 2) {
                        if (v < bA[m]) { b2A[m] = bA[m]; bA[m] = v; iA[m] = kidx; }
                        else b2A[m] = fminf(b2A[m], v);
                    } else {
                        if (v < bB[m]) { b2B[m] = bB[m]; bB[m] = v; iB[m] = kidx; }
                        else b2B[m] = fminf(b2B[m], v);
                    }
                }
            }
        }
        cp_wait0();
        __syncthreads();
    }

    // lane-quad merge (4 lanes share each row)
    #pragma unroll
    for (int m = 0; m < 2; m++) {
        #pragma unroll
        for (int off = 1; off <= 2; off <<= 1) {
            float ov = __shfl_xor_sync(0xffffffff, bA[m], off);
            float ov2 = __shfl_xor_sync(0xffffffff, b2A[m], off);
            int   oi = __shfl_xor_sync(0xffffffff, iA[m], off);
            if (ov < bA[m]) { b2A[m] = fminf(bA[m], ov2); bA[m] = ov; iA[m] = oi; }
            else b2A[m] = fminf(b2A[m], ov);
            ov = __shfl_xor_sync(0xffffffff, bB[m], off);
            ov2 = __shfl_xor_sync(0xffffffff, b2B[m], off);
            oi = __shfl_xor_sync(0xffffffff, iB[m], off);
            if (ov < bB[m]) { b2B[m] = fminf(bB[m], ov2); bB[m] = ov; iB[m] = oi; }
            else b2B[m] = fminf(b2B[m], ov);
        }
    }

    // cross-warp merge (par 0 vs par 1) via smem (A region is free now)
    float* mv  = (float*)smem;
    float* mv2 = (float*)(smem + 512);
    int*   mi  = (int*)(smem + 1024);
    int*   fi  = (int*)(smem + 1536);    // final per-row idx for the output phase
    float* ws  = (float*)(smem + 2048);
    __syncthreads();
    if (par == 1 && (lane & 3) == 0) {
        #pragma unroll
        for (int m = 0; m < 2; m++) {
            int rA = m0 + m * 16 + (lane >> 2);
            mv[rA] = bA[m]; mv2[rA] = b2A[m]; mi[rA] = iA[m];
            int rB = rA + 8;
            mv[rB] = bB[m]; mv2[rB] = b2B[m]; mi[rB] = iB[m];
        }
    }
    __syncthreads();
    if (par == 0 && (lane & 3) == 0) {
        #pragma unroll
        for (int m = 0; m < 2; m++) {
            #pragma unroll
            for (int half = 0; half < 2; half++) {
                int rr = m0 + m * 16 + half * 8 + (lane >> 2);
                float myb  = half ? bB[m]  : bA[m];
                float myb2 = half ? b2B[m] : b2A[m];
                int   myi  = half ? iB[m]  : iA[m];
                float ob = mv[rr], ob2 = mv2[rr]; int oi = mi[rr];
                float nb, nb2; int ni;
                if (ob < myb) { nb = ob; ni = oi; nb2 = fminf(myb, ob2); }
                else          { nb = myb; ni = myi; nb2 = fminf(myb2, ob); }
                int row = row0 + rr;
                d_idx[row] = ni;
                fi[rr] = ni;
                if (nb2 - nb < MARGIN_COARSE) { int p = atomicAdd(&d_flagCnt, 1); d_flagList[p] = row; }
            }
        }
    }
    __syncthreads();

    // ---- fused output phase: out = x + (q - x), loss partial ----
    float lv = 0.0f;
    #pragma unroll
    for (int i = 0; i < 8; i++) {
        int f = tid + i * 256;              // 2048 float4
        int row = f >> 4, j = f & 15;
        int idx = fi[row];
        float4 xv = ((const float4*)x)[(row0 + row) * 16 + j];
        float4 qv = *(const float4*)(d_eT + idx * D + 4 * j);
        float dx = qv.x - xv.x, dy = qv.y - xv.y, dz = qv.z - xv.z, dw = qv.w - xv.w;
        ((float4*)out)[(row0 + row) * 16 + j] =
            make_float4(xv.x + dx, xv.y + dy, xv.z + dz, xv.w + dw);
        lv += dx * dx + dy * dy + dz * dz + dw * dw;
    }
    #pragma unroll
    for (int off = 16; off > 0; off >>= 1) lv += __shfl_xor_sync(0xffffffff, lv, off);
    if (lane == 0) ws[warp] = lv;
    __syncthreads();
    if (tid == 0) {
        float s = 0.0f;
        #pragma unroll
        for (int i = 0; i < 8; i++) s += ws[i];
        atomicAdd(&d_lossAcc, s);
    }
}

// ---------------- exact resolve: fp32 screen + ff refine + output patch ----------------
__global__ __launch_bounds__(256, 2)
void exact_kernel(const float* __restrict__ x, const float* __restrict__ emb,
                  float* __restrict__ out) {
    __shared__ float sx[D];
    __shared__ float rbest[256];
    __shared__ unsigned long long spack;
    __shared__ float sdelta[2];
    int tid = threadIdx.x;

    int cnt = d_flagCnt;
    for (int i = blockIdx.x; i < cnt; i += gridDim.x) {
        int row = d_flagList[i];
        int oldIdx = d_idx[row];
        if (tid < D / 4) {
            float4 v = *(const float4*)(x + row * D + 4 * tid);
            sx[4*tid] = v.x; sx[4*tid+1] = v.y; sx[4*tid+2] = v.z; sx[4*tid+3] = v.w;
        }
        if (tid == 0) spack = ~0ull;
        __syncthreads();

        // phase 1: fp32 dots + ref-style norm
        float sn = 0.0f;
        float a0 = 0.f, a1 = 0.f, a2 = 0.f, a3 = 0.f;
        #pragma unroll 8
        for (int dd = 0; dd < D; dd++) {
            float xv = sx[dd];
            sn = __fadd_rn(sn, __fmul_rn(xv, xv));
            const float* er = emb + dd * K + tid;    // coalesced across lanes
            a0 = __fmaf_rn(xv, er[0],   a0);
            a1 = __fmaf_rn(xv, er[256], a1);
            a2 = __fmaf_rn(xv, er[512], a2);
            a3 = __fmaf_rn(xv, er[768], a3);
        }
        float xn = sn;
        float d32[4];
        d32[0] = d_en[tid]       - 2.0f * a0;
        d32[1] = d_en[tid + 256] - 2.0f * a1;
        d32[2] = d_en[tid + 512] - 2.0f * a2;
        d32[3] = d_en[tid + 768] - 2.0f * a3;
        float dmin = fminf(fminf(d32[0], d32[1]), fminf(d32[2], d32[3]));
        rbest[tid] = dmin;
        __syncthreads();
        for (int off = 128; off > 0; off >>= 1) {
            if (tid < off) rbest[tid] = fminf(rbest[tid], rbest[tid + off]);
            __syncthreads();
        }
        float best = rbest[0];

        // phase 2: exact (ref-grid-rounded) dist for screened candidates
        #pragma unroll
        for (int t = 0; t < 4; t++) {
            if (d32[t] < best + EPS_SCREEN) {
                int k = tid + 256 * t;
                float s = 0.f, c = 0.f;
                const float* ek = d_eT + k * D;
                #pragma unroll 8
                for (int dd = 0; dd < D; dd++) ddAccum(s, c, sx[dd], ek[dd]);
                float hi, lo;
                twoSum(s, c, hi, lo);
                float s2f = __fmaf_rn(2.0f, lo, __fmul_rn(2.0f, hi));   // fl32(2*sim)
                float t1 = __fadd_rn(xn, d_en[k]);
                float dist = __fsub_rn(t1, s2f);
                unsigned long long pk =
                    ((unsigned long long)__float_as_uint(dist) << 32) | (unsigned)k;
                atomicMin(&spack, pk);
            }
        }
        __syncthreads();
        int newIdx = (int)(spack & 0xFFFFFFFFull);
        if (tid == 0) d_idx[row] = newIdx;

        // output patch + loss delta for corrected rows
        if (newIdx != oldIdx) {
            if (tid < D) {
                float xvv = sx[tid];
                float qo = d_eT[oldIdx * D + tid];
                float qn = d_eT[newIdx * D + tid];
                float dof = qo - xvv, dn = qn - xvv;
                out[row * D + tid] = xvv + dn;
                float delta = dn * dn - dof * dof;
                #pragma unroll
                for (int off = 16; off > 0; off >>= 1)
                    delta += __shfl_xor_sync(0xffffffff, delta, off);
                if ((tid & 31) == 0) sdelta[tid >> 5] = delta;
            }
            __syncthreads();
            if (tid == 0) atomicAdd(&d_lossAcc, sdelta[0] + sdelta[1]);
        }
        __syncthreads();
    }
}

// ---------------- finalize loss ----------------
__global__ void fin_kernel(float* __restrict__ out, int out_size) {
    out[out_size - 1] = 1.25f * d_lossAcc * (1.0f / (float)(N_ROWS * D));
}

extern "C" void kernel_launch(void* const* d_in, const int* in_sizes, int n_in,
                              void* d_out, int out_size) {
    const float* x   = (const float*)d_in[0];
    const float* emb = (const float*)d_in[1];
    float* out = (float*)d_out;

    prep_kernel<<<32, 32>>>(emb);                              // idx 0
    noop_kernel<<<1, 1>>>();                                   // idx 1
    noop_kernel<<<1, 1>>>();                                   // idx 2
    gemm_argmin_kernel<<<N_ROWS / TM, 256, S_TOTAL>>>(x, out); // idx 3  (profiled)
    exact_kernel<<<512, 256>>>(x, emb, out);                   // idx 4
    fin_kernel<<<1, 1>>>(out, out_size);                       // idx 5
}